// round 1
// baseline (speedup 1.0000x reference)
#include <cuda_runtime.h>
#include <cstdint>

// Problem constants
#define BB   256
#define LL   50
#define DD   128
#define KK   4
#define VV   50000
#define VM1  49999
#define BL   (BB*LL)        // 12800
#define LEN_OPT 5
#define BETA_S 0.01f
#define EPS_N  1e-12f

// ---------------- scratch (static device globals; no allocation) ----------------
__device__ float g_hs   [BB*DD];
__device__ float g_hsw1 [BB*DD];
__device__ float g_lens [BB];
__device__ float g_nh   [BL*DD];        // tanh(cat @ w1)
__device__ float g_nh2  [BL*KK*DD];     // sigmoid(nh @ glu1_w + b)
__device__ float g_att  [BL*DD];        // tanh(hsW1 + hidden@att_w2)
__device__ float g_beta [BL*KK];
__device__ float g_selt [DD*BB*KK];     // select transposed: [d][b*4+k]
__device__ float g_invn [VM1];

__device__ __forceinline__ float sigmoidf(float x){ return 1.0f/(1.0f+expf(-x)); }

// ---------------- kernel 1: masked mean hs, lens, hs@att_w1 ----------------
__global__ void k_hs(const float* __restrict__ hidden, const int* __restrict__ mask,
                     const float* __restrict__ att_w1)
{
    int b = blockIdx.x, t = threadIdx.x;
    __shared__ float hs_sm[DD];
    float acc = 0.f, sm = 0.f;
    for (int l = 0; l < LL; l++) {
        float mk = (float)mask[b*LL + l];
        sm  += mk;
        acc += hidden[(b*LL + l)*DD + t] * mk;
    }
    float hsv = acc / sm;
    hs_sm[t] = hsv;
    g_hs[b*DD + t] = hsv;
    if (t == 0) g_lens[b] = sm - (float)LEN_OPT;
    __syncthreads();
    float a2 = 0.f;
    #pragma unroll 8
    for (int e = 0; e < DD; e++) a2 += hs_sm[e] * att_w1[e*DD + t];
    g_hsw1[b*DD + t] = a2;
}

// ---------------- front-end tiled GEMM: C[BL x NTOT] = act(A[BL x KDIM] @ W + ...) --
// MODE 0: A = concat(pos_emb, hidden), act = tanh           -> g_nh
// MODE 1: A = g_nh,  W = glu1_w, +bias, act = sigmoid       -> g_nh2
// MODE 2: A = hidden, W = att_w2, act = tanh(x + hsw1[b,n]) -> g_att
// 256 threads, Mt=64, Nt=64, thread tile 4x4, K-chunk 16.
template<int KDIM, int NTOT, int MODE>
__global__ void __launch_bounds__(256) k_gemm_front(
        const float* __restrict__ A, const float* __restrict__ W,
        const float* __restrict__ bias, float* __restrict__ C,
        const float* __restrict__ pos_emb, const float* __restrict__ hidden)
{
    __shared__ float Asm[16][64];   // [kc][m]
    __shared__ float Bsm[16][64];   // [kc][n]
    int tid = threadIdx.x;
    int tc = tid & 15, tr = tid >> 4;
    int nbase = blockIdx.x * 64, mbase = blockIdx.y * 64;

    float acc[4][4] = {};
    int mloc = tid & 63, kc0 = (tid >> 6) << 2;   // A-load mapping
    int kcW  = tid >> 4, nl4 = (tid & 15) << 2;   // W-load mapping

    for (int kk = 0; kk < KDIM; kk += 16) {
        __syncthreads();
        float4 av;
        if (MODE == 0) {
            int m  = mbase + mloc;
            int e0 = kk + kc0;
            if (e0 < 128) av = *(const float4*)(pos_emb + (m % LL)*DD + e0);
            else          av = *(const float4*)(hidden  + m*DD + (e0 - 128));
        } else {
            av = *(const float4*)(A + (size_t)(mbase + mloc)*KDIM + kk + kc0);
        }
        Asm[kc0+0][mloc]=av.x; Asm[kc0+1][mloc]=av.y;
        Asm[kc0+2][mloc]=av.z; Asm[kc0+3][mloc]=av.w;
        *(float4*)(&Bsm[kcW][nl4]) =
            *(const float4*)(W + (size_t)(kk + kcW)*NTOT + nbase + nl4);
        __syncthreads();
        #pragma unroll
        for (int kc = 0; kc < 16; kc++) {
            float4 a = *(float4*)(&Asm[kc][tr << 2]);
            float4 bv = *(float4*)(&Bsm[kc][tc << 2]);
            float aa[4] = {a.x, a.y, a.z, a.w};
            float bb[4] = {bv.x, bv.y, bv.z, bv.w};
            #pragma unroll
            for (int i = 0; i < 4; i++)
                #pragma unroll
                for (int j = 0; j < 4; j++)
                    acc[i][j] += aa[i]*bb[j];
        }
    }
    #pragma unroll
    for (int i = 0; i < 4; i++) {
        int m = mbase + (tr << 2) + i;
        float4 o;
        float* oo = &o.x;
        #pragma unroll
        for (int j = 0; j < 4; j++) {
            int n = nbase + (tc << 2) + j;
            float v = acc[i][j];
            if (MODE == 1)      v = sigmoidf(v + bias[n]);
            else if (MODE == 2) v = tanhf(v + g_hsw1[(m / LL)*DD + n]);
            else                v = tanhf(v);
            oo[j] = v;
        }
        *(float4*)(C + (size_t)m*NTOT + nbase + (tc << 2)) = o;
    }
}

// ---------------- beta & alpha fuse: g_beta = beta_raw*(0.5+alpha)*mask ------------
__global__ void k_beta_alpha(const int* __restrict__ mask,
                             const float* __restrict__ w2,
                             const float* __restrict__ att_v)
{
    int w = threadIdx.x >> 5, lane = threadIdx.x & 31;
    int m = blockIdx.x*4 + w;
    float bk[4] = {}, ak[4] = {};
    #pragma unroll
    for (int i = 0; i < 4; i++) {
        int d = lane + 32*i;
        float attv = g_att[m*DD + d];
        #pragma unroll
        for (int k = 0; k < 4; k++) {
            bk[k] += g_nh2[(size_t)m*512 + k*128 + d] * w2[d*4 + k];
            ak[k] += attv * att_v[d*4 + k];
        }
    }
    #pragma unroll
    for (int o = 16; o > 0; o >>= 1)
        #pragma unroll
        for (int k = 0; k < 4; k++) {
            bk[k] += __shfl_xor_sync(0xffffffffu, bk[k], o);
            ak[k] += __shfl_xor_sync(0xffffffffu, ak[k], o);
        }
    if (lane == 0) {
        float mk = (float)mask[m];
        #pragma unroll
        for (int k = 0; k < 4; k++)
            g_beta[m*4 + k] = bk[k] * (0.5f + sigmoidf(ak[k])) * mk;
    }
}

// ---------------- select (transposed layout [d][b*4+k]) ----------------------------
__global__ void k_select(const float* __restrict__ hidden)
{
    int b = blockIdx.x, t = threadIdx.x;   // t = d
    float acc[4] = {};
    for (int l = 0; l < LL; l++) {
        float h = hidden[(b*LL + l)*DD + t];
        float4 be = *(const float4*)(&g_beta[(b*LL + l)*4]);
        acc[0] += be.x*h; acc[1] += be.y*h; acc[2] += be.z*h; acc[3] += be.w*h;
    }
    #pragma unroll
    for (int k = 0; k < 4; k++)
        g_selt[(size_t)t*(BB*KK) + b*4 + k] = acc[k];
}

// ---------------- loss1 scalar ------------------------------------------------------
__global__ void k_loss(float* __restrict__ out_scalar)
{
    int b = threadIdx.x;
    float n2[4] = {};
    for (int l = 0; l < LL; l++) {
        float4 be = *(const float4*)(&g_beta[(b*LL + l)*4]);
        n2[0]+=be.x*be.x; n2[1]+=be.y*be.y; n2[2]+=be.z*be.z; n2[3]+=be.w*be.w;
    }
    float inv[4];
    #pragma unroll
    for (int k = 0; k < 4; k++) inv[k] = 1.0f / fmaxf(sqrtf(n2[k]), EPS_N);
    float G[6] = {};
    for (int l = 0; l < LL; l++) {
        float4 be = *(const float4*)(&g_beta[(b*LL + l)*4]);
        float v0=be.x*inv[0], v1=be.y*inv[1], v2=be.z*inv[2], v3=be.w*inv[3];
        G[0]+=v0*v1; G[1]+=v0*v2; G[2]+=v0*v3;
        G[3]+=v1*v2; G[4]+=v1*v3; G[5]+=v2*v3;
    }
    float sim = 0.f;
    #pragma unroll
    for (int i = 0; i < 6; i++) sim += fabsf(G[i]);
    sim *= (2.0f / (KK*(KK-1)));
    float lossb = sigmoidf(sim * g_lens[b]);
    __shared__ float red[BB];
    red[b] = lossb;  __syncthreads();
    for (int s = BB/2; s > 0; s >>= 1) {
        if (b < s) red[b] += red[b + s];
        __syncthreads();
    }
    if (b == 0) *out_scalar = red[0] * BETA_S;
}

// ---------------- emb row inverse norms --------------------------------------------
__global__ void k_invnorm(const float* __restrict__ emb)
{
    int w = threadIdx.x >> 5, lane = threadIdx.x & 31;
    int v = blockIdx.x*8 + w;
    if (v >= VM1) return;
    float4 x = *(const float4*)(emb + (size_t)(1 + v)*DD + lane*4);
    float s = x.x*x.x + x.y*x.y + x.z*x.z + x.w*x.w;
    #pragma unroll
    for (int o = 16; o > 0; o >>= 1) s += __shfl_xor_sync(0xffffffffu, s, o);
    if (lane == 0) g_invn[v] = 1.0f / fmaxf(sqrtf(s), EPS_N);
}

// ---------------- big GEMM: scores[k,b,v] + max over k ------------------------------
// Block: 16 b's x all 4 k (M=64) x 128 v.  256 threads, thread = (tr=b_local, tc),
// thread owns n = tc + 16*j (strided -> coalesced stores) and all 4 k of its b.
__global__ void __launch_bounds__(256) k_scores(const float* __restrict__ emb,
                                                float* __restrict__ maxsc,
                                                float* __restrict__ scores)
{
    __shared__ float Asm[DD][64];     // [d][b_local*4+k]
    __shared__ float Bsm[16][128];    // [kc][v_local]
    int tid = threadIdx.x;
    int tc = tid & 15, tr = tid >> 4;
    int vbase = blockIdx.x * 128;
    int bbase = blockIdx.y * 16;

    // A load (once): coalesced from transposed select
    for (int i = tid; i < 64*DD; i += 256) {
        int mloc = i & 63, d = i >> 6;
        Asm[d][mloc] = g_selt[(size_t)d*(BB*KK) + bbase*4 + mloc];
    }

    float acc[4][8] = {};
    int vloc = tid & 127, half = tid >> 7;
    int vg = vbase + vloc;  if (vg > VM1 - 1) vg = VM1 - 1;
    const float* erow = emb + (size_t)(1 + vg)*DD;

    for (int kk = 0; kk < DD; kk += 16) {
        __syncthreads();
        float4 x = *(const float4*)(erow + kk + half*8);
        float4 y = *(const float4*)(erow + kk + half*8 + 4);
        int r = half*8;
        Bsm[r+0][vloc]=x.x; Bsm[r+1][vloc]=x.y; Bsm[r+2][vloc]=x.z; Bsm[r+3][vloc]=x.w;
        Bsm[r+4][vloc]=y.x; Bsm[r+5][vloc]=y.y; Bsm[r+6][vloc]=y.z; Bsm[r+7][vloc]=y.w;
        __syncthreads();
        #pragma unroll
        for (int kc = 0; kc < 16; kc++) {
            float4 a = *(float4*)(&Asm[kk + kc][tr << 2]);
            float aa[4] = {a.x, a.y, a.z, a.w};
            #pragma unroll
            for (int j = 0; j < 8; j++) {
                float bv = Bsm[kc][tc + 16*j];
                acc[0][j] += aa[0]*bv;
                acc[1][j] += aa[1]*bv;
                acc[2][j] += aa[2]*bv;
                acc[3][j] += aa[3]*bv;
            }
        }
    }

    int bglob = bbase + tr;
    #pragma unroll
    for (int j = 0; j < 8; j++) {
        int v = vbase + tc + 16*j;
        if (v < VM1) {
            float w = g_invn[v];
            float mx = -3.402823466e38f;
            #pragma unroll
            for (int k = 0; k < 4; k++) {
                float s = acc[k][j] * w;
                scores[((size_t)k*BB + bglob)*VM1 + v] = s;
                mx = fmaxf(mx, s);
            }
            maxsc[(size_t)bglob*VM1 + v] = mx;
        }
    }
}

// ---------------- launch ------------------------------------------------------------
extern "C" void kernel_launch(void* const* d_in, const int* in_sizes, int n_in,
                              void* d_out, int out_size)
{
    const float* hidden  = (const float*)d_in[0];
    const int*   mask    = (const int*)  d_in[1];
    const float* pos_emb = (const float*)d_in[2];
    const float* w1      = (const float*)d_in[3];
    const float* w2      = (const float*)d_in[4];
    const float* glu1_w  = (const float*)d_in[5];
    const float* glu1_b  = (const float*)d_in[6];
    const float* att_w1  = (const float*)d_in[7];
    const float* att_w2  = (const float*)d_in[8];
    const float* att_v   = (const float*)d_in[9];
    const float* emb     = (const float*)d_in[10];

    float* out    = (float*)d_out;
    float* maxsc  = out;                                   // [B, Vm1]
    float* scalar = out + (size_t)BB*VM1;                  // [1]
    float* scores = out + (size_t)BB*VM1 + 1;              // [K, B, Vm1]

    // scratch pointers are device globals referenced directly by kernels
    float* g_nh_p;   cudaGetSymbolAddress((void**)&g_nh_p,  g_nh);
    float* g_nh2_p;  cudaGetSymbolAddress((void**)&g_nh2_p, g_nh2);
    float* g_att_p;  cudaGetSymbolAddress((void**)&g_att_p, g_att);

    k_hs<<<BB, 128>>>(hidden, mask, att_w1);

    k_gemm_front<256, 128, 0><<<dim3(2,   BL/64), 256>>>(nullptr, w1,     nullptr, g_nh_p,  pos_emb, hidden);
    k_gemm_front<128, 512, 1><<<dim3(8,   BL/64), 256>>>(g_nh_p,  glu1_w, glu1_b,  g_nh2_p, nullptr, nullptr);
    k_gemm_front<128, 128, 2><<<dim3(2,   BL/64), 256>>>(hidden,  att_w2, nullptr, g_att_p, nullptr, nullptr);

    k_beta_alpha<<<BL/4, 128>>>(mask, w2, att_v);
    k_select<<<BB, 128>>>(hidden);
    k_loss<<<1, BB>>>(scalar);
    k_invnorm<<<(VM1 + 7)/8, 256>>>(emb);

    k_scores<<<dim3((VM1 + 127)/128, BB/16), 256>>>(emb, maxsc, scores);
}

// round 3
// speedup vs baseline: 1.6810x; 1.6810x over previous
#include <cuda_runtime.h>
#include <cuda_bf16.h>
#include <cstdint>

// Problem constants
#define BB   256
#define LL   50
#define DD   128
#define KK   4
#define VV   50000
#define VM1  49999
#define BL   (BB*LL)        // 12800
#define LEN_OPT 5
#define BETA_S 0.01f
#define EPS_N  1e-12f

// Arch-specific (sm_103a) feature gate: tcgen05 only exists on the 'a' target.
#if defined(__CUDA_ARCH__)
#  if defined(__CUDA_ARCH_FEAT_SM103_ALL) || defined(__CUDA_ARCH_FEAT_SM100_ALL) || \
      defined(__CUDA_ARCH_FEAT_SM101_ALL) || \
      (defined(__CUDA_ARCH_SPECIFIC__) && (__CUDA_ARCH_SPECIFIC__ >= 1000)) || \
      (defined(__CUDA_ARCH_FAMILY_SPECIFIC__) && (__CUDA_ARCH_FAMILY_SPECIFIC__ >= 1000))
#    define HAS_TCGEN05 1
#  else
#    define HAS_TCGEN05 0
#  endif
#else
#  define HAS_TCGEN05 0
#endif

// ---------------- scratch (static device globals; no allocation) ----------------
__device__ float g_hs   [BB*DD];
__device__ float g_hsw1 [BB*DD];
__device__ float g_lens [BB];
__device__ float g_nh   [BL*DD];        // tanh(cat @ w1)
__device__ float g_nh2  [BL*KK*DD];     // sigmoid(nh @ glu1_w + b)
__device__ float g_att  [BL*DD];        // tanh(hsW1 + hidden@att_w2)
__device__ float g_beta [BL*KK];
__device__ __align__(16) __nv_bfloat16 g_sel_hi[BB*KK*DD];   // select rows [m=b*4+k][d]
__device__ __align__(16) __nv_bfloat16 g_sel_lo[BB*KK*DD];
__device__ __align__(16) __nv_bfloat16 g_emb_hi[(size_t)VM1*DD]; // normalized emb rows
__device__ __align__(16) __nv_bfloat16 g_emb_lo[(size_t)VM1*DD];

__device__ __forceinline__ float sigmoidf(float x){ return 1.0f/(1.0f+expf(-x)); }

__device__ __forceinline__ uint32_t smem_u32(const void* p) {
    uint32_t a;
    asm("{ .reg .u64 t; cvta.to.shared.u64 t, %1; cvt.u32.u64 %0, t; }" : "=r"(a) : "l"(p));
    return a;
}
#define SWZ128(x) ((x) ^ (((x) >> 3) & 0x70))

static constexpr uint64_t SMEM_DESC_BASE_SW128 =
    (uint64_t(2) << 61) | (uint64_t(1) << 46) | (uint64_t(64) << 32) | (uint64_t(1) << 16);
#define MAKE_DESC(addr) (SMEM_DESC_BASE_SW128 | ((uint64_t)((addr) >> 4) & 0x3FFF))

// ---------------- kernel 1: masked mean hs, lens, hs@att_w1 ----------------
__global__ void k_hs(const float* __restrict__ hidden, const int* __restrict__ mask,
                     const float* __restrict__ att_w1)
{
    int b = blockIdx.x, t = threadIdx.x;
    __shared__ float hs_sm[DD];
    float acc = 0.f, sm = 0.f;
    for (int l = 0; l < LL; l++) {
        float mk = (float)mask[b*LL + l];
        sm  += mk;
        acc += hidden[(b*LL + l)*DD + t] * mk;
    }
    float hsv = acc / sm;
    hs_sm[t] = hsv;
    g_hs[b*DD + t] = hsv;
    if (t == 0) g_lens[b] = sm - (float)LEN_OPT;
    __syncthreads();
    float a2 = 0.f;
    #pragma unroll 8
    for (int e = 0; e < DD; e++) a2 += hs_sm[e] * att_w1[e*DD + t];
    g_hsw1[b*DD + t] = a2;
}

// ---------------- front-end tiled GEMM -------------------------
template<int KDIM, int NTOT, int MODE>
__global__ void __launch_bounds__(256) k_gemm_front(
        const float* __restrict__ A, const float* __restrict__ W,
        const float* __restrict__ bias, float* __restrict__ C,
        const float* __restrict__ pos_emb, const float* __restrict__ hidden)
{
    __shared__ float Asm[16][64];   // [kc][m]
    __shared__ float Bsm[16][64];   // [kc][n]
    int tid = threadIdx.x;
    int tc = tid & 15, tr = tid >> 4;
    int nbase = blockIdx.x * 64, mbase = blockIdx.y * 64;

    float acc[4][4] = {};
    int mloc = tid & 63, kc0 = (tid >> 6) << 2;
    int kcW  = tid >> 4, nl4 = (tid & 15) << 2;

    for (int kk = 0; kk < KDIM; kk += 16) {
        __syncthreads();
        float4 av;
        if (MODE == 0) {
            int m  = mbase + mloc;
            int e0 = kk + kc0;
            if (e0 < 128) av = *(const float4*)(pos_emb + (m % LL)*DD + e0);
            else          av = *(const float4*)(hidden  + m*DD + (e0 - 128));
        } else {
            av = *(const float4*)(A + (size_t)(mbase + mloc)*KDIM + kk + kc0);
        }
        Asm[kc0+0][mloc]=av.x; Asm[kc0+1][mloc]=av.y;
        Asm[kc0+2][mloc]=av.z; Asm[kc0+3][mloc]=av.w;
        *(float4*)(&Bsm[kcW][nl4]) =
            *(const float4*)(W + (size_t)(kk + kcW)*NTOT + nbase + nl4);
        __syncthreads();
        #pragma unroll
        for (int kc = 0; kc < 16; kc++) {
            float4 a = *(float4*)(&Asm[kc][tr << 2]);
            float4 bv = *(float4*)(&Bsm[kc][tc << 2]);
            float aa[4] = {a.x, a.y, a.z, a.w};
            float bb[4] = {bv.x, bv.y, bv.z, bv.w};
            #pragma unroll
            for (int i = 0; i < 4; i++)
                #pragma unroll
                for (int j = 0; j < 4; j++)
                    acc[i][j] += aa[i]*bb[j];
        }
    }
    #pragma unroll
    for (int i = 0; i < 4; i++) {
        int m = mbase + (tr << 2) + i;
        float4 o;
        float* oo = &o.x;
        #pragma unroll
        for (int j = 0; j < 4; j++) {
            int n = nbase + (tc << 2) + j;
            float v = acc[i][j];
            if (MODE == 1)      v = sigmoidf(v + bias[n]);
            else if (MODE == 2) v = tanhf(v + g_hsw1[(m / LL)*DD + n]);
            else                v = tanhf(v);
            oo[j] = v;
        }
        *(float4*)(C + (size_t)m*NTOT + nbase + (tc << 2)) = o;
    }
}

// ---------------- beta & alpha fuse ------------------------------------------------
__global__ void k_beta_alpha(const int* __restrict__ mask,
                             const float* __restrict__ w2,
                             const float* __restrict__ att_v)
{
    int w = threadIdx.x >> 5, lane = threadIdx.x & 31;
    int m = blockIdx.x*4 + w;
    float bk[4] = {}, ak[4] = {};
    #pragma unroll
    for (int i = 0; i < 4; i++) {
        int d = lane + 32*i;
        float attv = g_att[m*DD + d];
        #pragma unroll
        for (int k = 0; k < 4; k++) {
            bk[k] += g_nh2[(size_t)m*512 + k*128 + d] * w2[d*4 + k];
            ak[k] += attv * att_v[d*4 + k];
        }
    }
    #pragma unroll
    for (int o = 16; o > 0; o >>= 1)
        #pragma unroll
        for (int k = 0; k < 4; k++) {
            bk[k] += __shfl_xor_sync(0xffffffffu, bk[k], o);
            ak[k] += __shfl_xor_sync(0xffffffffu, ak[k], o);
        }
    if (lane == 0) {
        float mk = (float)mask[m];
        #pragma unroll
        for (int k = 0; k < 4; k++)
            g_beta[m*4 + k] = bk[k] * (0.5f + sigmoidf(ak[k])) * mk;
    }
}

// ---------------- select -> bf16 hi/lo rows [m=b*4+k][d] ---------------------------
__global__ void k_select(const float* __restrict__ hidden)
{
    int b = blockIdx.x, t = threadIdx.x;   // t = d
    float acc[4] = {};
    for (int l = 0; l < LL; l++) {
        float h = hidden[(b*LL + l)*DD + t];
        float4 be = *(const float4*)(&g_beta[(b*LL + l)*4]);
        acc[0] += be.x*h; acc[1] += be.y*h; acc[2] += be.z*h; acc[3] += be.w*h;
    }
    #pragma unroll
    for (int k = 0; k < 4; k++) {
        float v = acc[k];
        __nv_bfloat16 hi = __float2bfloat16(v);
        __nv_bfloat16 lo = __float2bfloat16(v - __bfloat162float(hi));
        g_sel_hi[(b*4 + k)*DD + t] = hi;
        g_sel_lo[(b*4 + k)*DD + t] = lo;
    }
}

// ---------------- loss1 scalar -----------------------------------------------------
__global__ void k_loss(float* __restrict__ out_scalar)
{
    int b = threadIdx.x;
    float n2[4] = {};
    for (int l = 0; l < LL; l++) {
        float4 be = *(const float4*)(&g_beta[(b*LL + l)*4]);
        n2[0]+=be.x*be.x; n2[1]+=be.y*be.y; n2[2]+=be.z*be.z; n2[3]+=be.w*be.w;
    }
    float inv[4];
    #pragma unroll
    for (int k = 0; k < 4; k++) inv[k] = 1.0f / fmaxf(sqrtf(n2[k]), EPS_N);
    float G[6] = {};
    for (int l = 0; l < LL; l++) {
        float4 be = *(const float4*)(&g_beta[(b*LL + l)*4]);
        float v0=be.x*inv[0], v1=be.y*inv[1], v2=be.z*inv[2], v3=be.w*inv[3];
        G[0]+=v0*v1; G[1]+=v0*v2; G[2]+=v0*v3;
        G[3]+=v1*v2; G[4]+=v1*v3; G[5]+=v2*v3;
    }
    float sim = 0.f;
    #pragma unroll
    for (int i = 0; i < 6; i++) sim += fabsf(G[i]);
    sim *= (2.0f / (KK*(KK-1)));
    float lossb = sigmoidf(sim * g_lens[b]);
    __shared__ float red[BB];
    red[b] = lossb;  __syncthreads();
    for (int s = BB/2; s > 0; s >>= 1) {
        if (b < s) red[b] += red[b + s];
        __syncthreads();
    }
    if (b == 0) *out_scalar = red[0] * BETA_S;
}

// ---------------- emb: normalize rows + bf16 hi/lo split ---------------------------
__global__ void k_prep_emb(const float* __restrict__ emb)
{
    int w = threadIdx.x >> 5, lane = threadIdx.x & 31;
    int v = blockIdx.x*8 + w;
    if (v >= VM1) return;
    float4 x = *(const float4*)(emb + (size_t)(1 + v)*DD + lane*4);
    float s = x.x*x.x + x.y*x.y + x.z*x.z + x.w*x.w;
    #pragma unroll
    for (int o = 16; o > 0; o >>= 1) s += __shfl_xor_sync(0xffffffffu, s, o);
    float inv = 1.0f / fmaxf(sqrtf(s), EPS_N);
    float n[4] = {x.x*inv, x.y*inv, x.z*inv, x.w*inv};
    __nv_bfloat16 hi[4], lo[4];
    #pragma unroll
    for (int i = 0; i < 4; i++) {
        hi[i] = __float2bfloat16(n[i]);
        lo[i] = __float2bfloat16(n[i] - __bfloat162float(hi[i]));
    }
    *(uint64_t*)(&g_emb_hi[(size_t)v*DD + lane*4]) = *(uint64_t*)hi;
    *(uint64_t*)(&g_emb_lo[(size_t)v*DD + lane*4]) = *(uint64_t*)lo;
}

// ---------------- big GEMM: scores[k,b,v] + k-max ----------------------------------
// Tensor path (sm_103a): M=128 (32 b x 4 k), N=256 (v), K=128 (d).
// 3 bf16 passes: AhBh + AhBl + AlBh into one fp32 TMEM accumulator.
#define TILE_N 256
#define MMA_IDESC ((1u<<4) | (1u<<7) | (1u<<10) | ((TILE_N/8)<<17) | ((128/16)<<24))

// smem layout (bytes)
#define OFF_TMEM 0
#define OFF_MBAR 8
#define OFF_AH   1024
#define OFF_AL   (OFF_AH + 32768)
#define OFF_BH   (OFF_AL + 32768)
#define OFF_BL   (OFF_BH + 65536)
#define SMEM_TOT (OFF_BL + 65536)
// epilogue staging (aliases A region, used only after MMA completes)
#define OFF_STG  1024
#define OFF_MSTG (OFF_STG + 4*32*33*4)

#if HAS_TCGEN05
__device__ __forceinline__ uint32_t elect1() {
    uint32_t p;
    asm volatile("{ .reg .pred p; elect.sync _|p, 0xFFFFFFFF; selp.b32 %0,1,0,p; }" : "=r"(p));
    return p;
}
__device__ __forceinline__ void mma_f16_ss(uint32_t d_tmem, uint64_t a_desc,
                                           uint64_t b_desc, uint32_t idesc, int en)
{
    asm volatile(
        "{\n\t.reg .pred p;\n\t"
        "setp.ne.u32 p, %4, 0;\n\t"
        "tcgen05.mma.cta_group::1.kind::f16 [%0], %1, %2, %3, {%5,%5,%5,%5}, p;\n\t}"
        :: "r"(d_tmem), "l"(a_desc), "l"(b_desc), "r"(idesc), "r"(en), "r"(0u)
        : "memory");
}
#endif

__global__ void __launch_bounds__(256, 1) k_scores_mma(
        float* __restrict__ maxsc, float* __restrict__ scores)
{
#if HAS_TCGEN05
    extern __shared__ char smem[];
    uint32_t sbase = smem_u32(smem);
    int tid = threadIdx.x;
    int wid = tid >> 5, lane = tid & 31;
    int mtile = blockIdx.x;            // 0..7
    int vbase = blockIdx.y * TILE_N;

    if (tid == 0) {
        asm volatile("mbarrier.init.shared.b64 [%0], 1;" :: "r"(sbase + OFF_MBAR) : "memory");
    }
    if (wid == 4) {
        asm volatile("tcgen05.alloc.cta_group::1.sync.aligned.shared::cta.b32 [%0], %1;"
                     :: "r"(sbase + OFF_TMEM), "r"(256u) : "memory");
    }
    __syncthreads();
    uint32_t tmem;
    asm volatile("ld.shared.b32 %0, [%1];" : "=r"(tmem) : "r"(sbase + OFF_TMEM));

    // ---- stage A tiles (128 x 128 bf16, hi & lo), blocked SW128 atom layout ----
    {
        const __nv_bfloat16* srcs[2] = { g_sel_hi, g_sel_lo };
        uint32_t offs[2] = { OFF_AH, OFF_AL };
        #pragma unroll
        for (int h = 0; h < 2; h++) {
            for (int i = tid; i < 128*16; i += 256) {
                int r = i >> 4, c8 = i & 15;
                uint32_t byte = (uint32_t)((c8 >> 3)*16 + (r >> 3))*1024u
                              + (uint32_t)(r & 7)*128u + (uint32_t)(c8 & 7)*16u;
                uint4 val = *(const uint4*)(srcs[h] + (mtile*128 + r)*DD + (c8 & 7)*8 + (c8 >> 3)*64);
                *(uint4*)(smem + offs[h] + SWZ128(byte)) = val;
            }
        }
    }
    // ---- stage B tiles (256 x 128 bf16, hi & lo) ----
    {
        const __nv_bfloat16* srcs[2] = { g_emb_hi, g_emb_lo };
        uint32_t offs[2] = { OFF_BH, OFF_BL };
        #pragma unroll
        for (int h = 0; h < 2; h++) {
            for (int i = tid; i < 256*16; i += 256) {
                int r = i >> 4, c8 = i & 15;
                int v = vbase + r; if (v > VM1 - 1) v = VM1 - 1;
                uint32_t byte = (uint32_t)((c8 >> 3)*32 + (r >> 3))*1024u
                              + (uint32_t)(r & 7)*128u + (uint32_t)(c8 & 7)*16u;
                uint4 val = *(const uint4*)(srcs[h] + (size_t)v*DD + (c8 & 7)*8 + (c8 >> 3)*64);
                *(uint4*)(smem + offs[h] + SWZ128(byte)) = val;
            }
        }
    }
    __syncthreads();

    // ---- MMA: 3 passes x 8 K-steps into TMEM D[128 x 256] ----
    if (wid == 4) {
        if (elect1()) {
            asm volatile("fence.proxy.async.shared::cta;" ::: "memory");
            uint64_t dAh = MAKE_DESC(sbase + OFF_AH);
            uint64_t dAl = MAKE_DESC(sbase + OFF_AL);
            uint64_t dBh = MAKE_DESC(sbase + OFF_BH);
            uint64_t dBl = MAKE_DESC(sbase + OFF_BL);
            uint64_t ad[3] = { dAh, dAh, dAl };
            uint64_t bd[3] = { dBh, dBl, dBh };
            #pragma unroll
            for (int p = 0; p < 3; p++) {
                #pragma unroll
                for (int s = 0; s < 8; s++) {
                    uint64_t a = ad[p] + (uint64_t)((s >> 2)*1024 + (s & 3)*2);
                    uint64_t b = bd[p] + (uint64_t)((s >> 2)*2048 + (s & 3)*2);
                    mma_f16_ss(tmem, a, b, MMA_IDESC, !(p == 0 && s == 0));
                }
            }
            asm volatile(
                "tcgen05.commit.cta_group::1.mbarrier::arrive::one.shared::cluster.b64 [%0];"
                :: "r"(sbase + OFF_MBAR) : "memory");
        }
    }
    __syncthreads();

    {
        uint32_t mbar = sbase + OFF_MBAR;
        asm volatile(
            "{\n\t.reg .pred P1;\n\t"
            "WL_%=:\n\t"
            "mbarrier.try_wait.parity.acquire.cta.shared::cta.b64 P1, [%0], 0, 0x989680;\n\t"
            "@P1 bra.uni WD_%=;\n\t"
            "bra.uni WL_%=;\n\t"
            "WD_%=:\n\t}"
            :: "r"(mbar) : "memory");
    }
    asm volatile("tcgen05.fence::after_thread_sync;" ::: "memory");

    // ---- epilogue: warps 0-3 read TMEM, stage via smem, coalesced stores + k-max
    if (wid < 4) {
        float* stg  = (float*)(smem + OFF_STG  + wid*(32*33*4));
        float* mstg = (float*)(smem + OFF_MSTG + wid*(8*33*4));
        #pragma unroll 1
        for (int chunk = 0; chunk < TILE_N/32; chunk++) {
            uint32_t r[32];
            asm volatile(
                "tcgen05.ld.sync.aligned.32x32b.x32.b32 "
                "{%0,%1,%2,%3,%4,%5,%6,%7,%8,%9,%10,%11,%12,%13,%14,%15,"
                "%16,%17,%18,%19,%20,%21,%22,%23,%24,%25,%26,%27,%28,%29,%30,%31}, [%32];"
                : "=r"(r[0]),"=r"(r[1]),"=r"(r[2]),"=r"(r[3]),"=r"(r[4]),"=r"(r[5]),"=r"(r[6]),"=r"(r[7]),
                  "=r"(r[8]),"=r"(r[9]),"=r"(r[10]),"=r"(r[11]),"=r"(r[12]),"=r"(r[13]),"=r"(r[14]),"=r"(r[15]),
                  "=r"(r[16]),"=r"(r[17]),"=r"(r[18]),"=r"(r[19]),"=r"(r[20]),"=r"(r[21]),"=r"(r[22]),"=r"(r[23]),
                  "=r"(r[24]),"=r"(r[25]),"=r"(r[26]),"=r"(r[27]),"=r"(r[28]),"=r"(r[29]),"=r"(r[30]),"=r"(r[31])
                : "r"(tmem + chunk*32));
            asm volatile("tcgen05.wait::ld.sync.aligned;" ::: "memory");

            #pragma unroll
            for (int c = 0; c < 32; c++) {
                float v = __uint_as_float(r[c]);
                stg[lane*33 + c] = v;
                float mx = v;
                mx = fmaxf(mx, __shfl_xor_sync(0xffffffffu, mx, 1));
                mx = fmaxf(mx, __shfl_xor_sync(0xffffffffu, mx, 2));
                if ((lane & 3) == 0) mstg[(lane >> 2)*33 + c] = mx;
            }
            __syncwarp();

            int v = vbase + chunk*32 + lane;
            if (v < VM1) {
                #pragma unroll 4
                for (int rr = 0; rr < 32; rr++) {
                    int m = wid*32 + rr;
                    int k = m & 3;
                    int b = mtile*32 + (m >> 2);
                    scores[((size_t)k*BB + b)*VM1 + v] = stg[rr*33 + lane];
                }
                #pragma unroll
                for (int rr = 0; rr < 8; rr++) {
                    int b = mtile*32 + wid*8 + rr;
                    maxsc[(size_t)b*VM1 + v] = mstg[rr*33 + lane];
                }
            }
            __syncwarp();
        }
    }
    __syncthreads();
    if (wid == 4) {
        asm volatile("tcgen05.dealloc.cta_group::1.sync.aligned.b32 %0, %1;"
                     :: "r"(tmem), "r"(256u));
    }
#else
    // ------- fp32 fallback (compiled for non-'a' targets; correct, not fast) -------
    extern __shared__ char smem[];
    float* Af = (float*)smem;                 // [d][m]  128x128
    float* Bf = (float*)(smem + 65536);       // [d][v]  128x128
    int tid = threadIdx.x;
    int tc = tid & 15, tr = tid >> 4;
    int mtile = blockIdx.x;
    int vbase = blockIdx.y * TILE_N;

    for (int i = tid; i < 128*128; i += 256) {
        int r = i >> 7, d = i & 127;
        int row = mtile*128 + r;
        float v = __bfloat162float(g_sel_hi[row*DD + d]) + __bfloat162float(g_sel_lo[row*DD + d]);
        Af[d*128 + r] = v;
    }
    #pragma unroll 1
    for (int half = 0; half < 2; half++) {
        __syncthreads();
        for (int i = tid; i < 128*128; i += 256) {
            int r = i >> 7, d = i & 127;
            int v = vbase + half*128 + r; if (v > VM1 - 1) v = VM1 - 1;
            Bf[d*128 + r] = __bfloat162float(g_emb_hi[(size_t)v*DD + d])
                          + __bfloat162float(g_emb_lo[(size_t)v*DD + d]);
        }
        __syncthreads();
        float acc[8][8] = {};
        for (int kc = 0; kc < 128; kc++) {
            float4 a0 = *(float4*)(Af + kc*128 + tr*8);
            float4 a1 = *(float4*)(Af + kc*128 + tr*8 + 4);
            float aa[8] = {a0.x,a0.y,a0.z,a0.w,a1.x,a1.y,a1.z,a1.w};
            #pragma unroll
            for (int j = 0; j < 8; j++) {
                float bv = Bf[kc*128 + tc + 16*j];
                #pragma unroll
                for (int i = 0; i < 8; i++) acc[i][j] += aa[i]*bv;
            }
        }
        #pragma unroll
        for (int j = 0; j < 8; j++) {
            int v = vbase + half*128 + tc + 16*j;
            if (v < VM1) {
                float mx0 = -3.402823466e38f, mx1 = mx0;
                #pragma unroll
                for (int i = 0; i < 8; i++) {
                    int m = tr*8 + i;
                    int k = m & 3;
                    int b = mtile*32 + (m >> 2);
                    scores[((size_t)k*BB + b)*VM1 + v] = acc[i][j];
                    if (i < 4) mx0 = fmaxf(mx0, acc[i][j]);
                    else       mx1 = fmaxf(mx1, acc[i][j]);
                }
                maxsc[(size_t)(mtile*32 + tr*2 + 0)*VM1 + v] = mx0;
                maxsc[(size_t)(mtile*32 + tr*2 + 1)*VM1 + v] = mx1;
            }
        }
    }
#endif
}

// ---------------- launch ------------------------------------------------------------
extern "C" void kernel_launch(void* const* d_in, const int* in_sizes, int n_in,
                              void* d_out, int out_size)
{
    const float* hidden  = (const float*)d_in[0];
    const int*   mask    = (const int*)  d_in[1];
    const float* pos_emb = (const float*)d_in[2];
    const float* w1      = (const float*)d_in[3];
    const float* w2      = (const float*)d_in[4];
    const float* glu1_w  = (const float*)d_in[5];
    const float* glu1_b  = (const float*)d_in[6];
    const float* att_w1  = (const float*)d_in[7];
    const float* att_w2  = (const float*)d_in[8];
    const float* att_v   = (const float*)d_in[9];
    const float* emb     = (const float*)d_in[10];

    float* out    = (float*)d_out;
    float* maxsc  = out;                                   // [B, Vm1]
    float* scalar = out + (size_t)BB*VM1;                  // [1]
    float* scores = out + (size_t)BB*VM1 + 1;              // [K, B, Vm1]

    float* g_nh_p;   cudaGetSymbolAddress((void**)&g_nh_p,  g_nh);
    float* g_nh2_p;  cudaGetSymbolAddress((void**)&g_nh2_p, g_nh2);
    float* g_att_p;  cudaGetSymbolAddress((void**)&g_att_p, g_att);

    cudaFuncSetAttribute(k_scores_mma,
                         cudaFuncAttributeMaxDynamicSharedMemorySize, SMEM_TOT);

    k_prep_emb<<<(VM1 + 7)/8, 256>>>(emb);
    k_hs<<<BB, 128>>>(hidden, mask, att_w1);

    k_gemm_front<256, 128, 0><<<dim3(2, BL/64), 256>>>(nullptr, w1,     nullptr, g_nh_p,  pos_emb, hidden);
    k_gemm_front<128, 512, 1><<<dim3(8, BL/64), 256>>>(g_nh_p,  glu1_w, glu1_b,  g_nh2_p, nullptr, nullptr);
    k_gemm_front<128, 128, 2><<<dim3(2, BL/64), 256>>>(hidden,  att_w2, nullptr, g_att_p, nullptr, nullptr);

    k_beta_alpha<<<BL/4, 128>>>(mask, w2, att_v);
    k_select<<<BB, 128>>>(hidden);
    k_loss<<<1, BB>>>(scalar);

    k_scores_mma<<<dim3(8, (VM1 + TILE_N - 1)/TILE_N), 256, SMEM_TOT>>>(maxsc, scores);
}

// round 6
// speedup vs baseline: 2.0006x; 1.1901x over previous
#include <cuda_runtime.h>
#include <cuda_bf16.h>
#include <cstdint>

// Problem constants
#define BB   256
#define LL   50
#define DD   128
#define KK   4
#define VV   50000
#define VM1  49999
#define BL   (BB*LL)        // 12800
#define LEN_OPT 5
#define BETA_S 0.01f
#define EPS_N  1e-12f

// Arch-specific (sm_103a) feature gate: tcgen05 only exists on the 'a' target.
#if defined(__CUDA_ARCH__)
#  if defined(__CUDA_ARCH_FEAT_SM103_ALL) || defined(__CUDA_ARCH_FEAT_SM100_ALL) || \
      defined(__CUDA_ARCH_FEAT_SM101_ALL) || \
      (defined(__CUDA_ARCH_SPECIFIC__) && (__CUDA_ARCH_SPECIFIC__ >= 1000)) || \
      (defined(__CUDA_ARCH_FAMILY_SPECIFIC__) && (__CUDA_ARCH_FAMILY_SPECIFIC__ >= 1000))
#    define HAS_TCGEN05 1
#  else
#    define HAS_TCGEN05 0
#  endif
#else
#  define HAS_TCGEN05 0
#endif

// ---------------- scratch (static device globals; no allocation) ----------------
__device__ float g_hs   [BB*DD];
__device__ float g_hsw1 [BB*DD];
__device__ float g_lens [BB];
__device__ float g_beta [BL*KK];
__device__ float g_alpha[BL*KK];
__device__ __align__(16) __nv_bfloat16 g_nh_hi[BL*DD];       // tanh(cat@w1) split
__device__ __align__(16) __nv_bfloat16 g_nh_lo[BL*DD];
__device__ __align__(16) __nv_bfloat16 g_sel_hi[BB*KK*DD];   // select rows [m=b*4+k][d]
__device__ __align__(16) __nv_bfloat16 g_sel_lo[BB*KK*DD];
__device__ __align__(16) __nv_bfloat16 g_emb_hi[(size_t)VM1*DD]; // normalized emb rows
__device__ __align__(16) __nv_bfloat16 g_emb_lo[(size_t)VM1*DD];
// weights in B-operand layout [n][k], bf16 hi/lo
__device__ __align__(16) __nv_bfloat16 g_w1b_hi[128*256],  g_w1b_lo[128*256];
__device__ __align__(16) __nv_bfloat16 g_glub_hi[512*128], g_glub_lo[512*128];
__device__ __align__(16) __nv_bfloat16 g_aw2b_hi[128*128], g_aw2b_lo[128*128];

__device__ __forceinline__ float sigmoidf(float x){ return 1.0f/(1.0f+expf(-x)); }

__device__ __forceinline__ uint32_t smem_u32(const void* p) {
    uint32_t a;
    asm("{ .reg .u64 t; cvta.to.shared.u64 t, %1; cvt.u32.u64 %0, t; }" : "=r"(a) : "l"(p));
    return a;
}
#define SWZ128(x) ((x) ^ (((x) >> 3) & 0x70))

static constexpr uint64_t SMEM_DESC_BASE_SW128 =
    (uint64_t(2) << 61) | (uint64_t(1) << 46) | (uint64_t(64) << 32) | (uint64_t(1) << 16);
#define MAKE_DESC(addr) (SMEM_DESC_BASE_SW128 | ((uint64_t)((addr) >> 4) & 0x3FFF))

#if HAS_TCGEN05
__device__ __forceinline__ uint32_t elect1() {
    uint32_t p;
    asm volatile("{ .reg .pred p; elect.sync _|p, 0xFFFFFFFF; selp.b32 %0,1,0,p; }" : "=r"(p));
    return p;
}
__device__ __forceinline__ void mma_f16_ss(uint32_t d_tmem, uint64_t a_desc,
                                           uint64_t b_desc, uint32_t idesc, int en)
{
    asm volatile(
        "{\n\t.reg .pred p;\n\t"
        "setp.ne.u32 p, %4, 0;\n\t"
        "tcgen05.mma.cta_group::1.kind::f16 [%0], %1, %2, %3, {%5,%5,%5,%5}, p;\n\t}"
        :: "r"(d_tmem), "l"(a_desc), "l"(b_desc), "r"(idesc), "r"(en), "r"(0u)
        : "memory");
}
#define MBAR_WAIT(mbar, par) do {                                              \
    asm volatile(                                                              \
        "{\n\t.reg .pred P1;\n\t"                                              \
        "WL_%=:\n\t"                                                           \
        "mbarrier.try_wait.parity.acquire.cta.shared::cta.b64 P1, [%0], %1, 0x989680;\n\t" \
        "@P1 bra.uni WD_%=;\n\t"                                               \
        "bra.uni WL_%=;\n\t"                                                   \
        "WD_%=:\n\t}" :: "r"(mbar), "r"(par) : "memory");                      \
} while(0)
#define LDTM32(r, addr)                                                        \
    asm volatile(                                                              \
        "tcgen05.ld.sync.aligned.32x32b.x32.b32 "                              \
        "{%0,%1,%2,%3,%4,%5,%6,%7,%8,%9,%10,%11,%12,%13,%14,%15,"              \
        "%16,%17,%18,%19,%20,%21,%22,%23,%24,%25,%26,%27,%28,%29,%30,%31}, [%32];" \
        : "=r"(r[0]),"=r"(r[1]),"=r"(r[2]),"=r"(r[3]),"=r"(r[4]),"=r"(r[5]),"=r"(r[6]),"=r"(r[7]), \
          "=r"(r[8]),"=r"(r[9]),"=r"(r[10]),"=r"(r[11]),"=r"(r[12]),"=r"(r[13]),"=r"(r[14]),"=r"(r[15]), \
          "=r"(r[16]),"=r"(r[17]),"=r"(r[18]),"=r"(r[19]),"=r"(r[20]),"=r"(r[21]),"=r"(r[22]),"=r"(r[23]), \
          "=r"(r[24]),"=r"(r[25]),"=r"(r[26]),"=r"(r[27]),"=r"(r[28]),"=r"(r[29]),"=r"(r[30]),"=r"(r[31]) \
        : "r"(addr))
#endif

__device__ __forceinline__ ushort bf_hi_us(float v, float& rem) {
    __nv_bfloat16 hb = __float2bfloat16(v);
    rem = v - __bfloat162float(hb);
    return *reinterpret_cast<ushort*>(&hb);
}
__device__ __forceinline__ ushort bf_us(float v) {
    __nv_bfloat16 b = __float2bfloat16(v);
    return *reinterpret_cast<ushort*>(&b);
}

// ---------------- kernel 1: masked mean hs, lens, hs@att_w1 ----------------
__global__ void k_hs(const float* __restrict__ hidden, const int* __restrict__ mask,
                     const float* __restrict__ att_w1)
{
    int b = blockIdx.x, t = threadIdx.x;
    __shared__ float hs_sm[DD];
    float acc = 0.f, sm = 0.f;
    for (int l = 0; l < LL; l++) {
        float mk = (float)mask[b*LL + l];
        sm  += mk;
        acc += hidden[(b*LL + l)*DD + t] * mk;
    }
    float hsv = acc / sm;
    hs_sm[t] = hsv;
    g_hs[b*DD + t] = hsv;
    if (t == 0) g_lens[b] = sm - (float)LEN_OPT;
    __syncthreads();
    float a2 = 0.f;
    #pragma unroll 8
    for (int e = 0; e < DD; e++) a2 += hs_sm[e] * att_w1[e*DD + t];
    g_hsw1[b*DD + t] = a2;
}

// ---------------- weight prep: transpose + bf16 hi/lo split ------------------------
__global__ void k_prep_w(const float* __restrict__ w1, const float* __restrict__ glu1_w,
                         const float* __restrict__ att_w2)
{
    int i = blockIdx.x*256 + threadIdx.x;
    float v; __nv_bfloat16 hi, lo;
    if (i < 32768) {                 // w1 [256k,128n] -> [128n][256k]
        int n = i >> 8, k = i & 255;
        v = w1[k*128 + n];
        hi = __float2bfloat16(v); lo = __float2bfloat16(v - __bfloat162float(hi));
        g_w1b_hi[i] = hi; g_w1b_lo[i] = lo;
    } else if (i < 32768 + 65536) {  // glu1_w [128k,512n] -> [512n][128k]
        int j = i - 32768;
        int n = j >> 7, k = j & 127;
        v = glu1_w[k*512 + n];
        hi = __float2bfloat16(v); lo = __float2bfloat16(v - __bfloat162float(hi));
        g_glub_hi[j] = hi; g_glub_lo[j] = lo;
    } else if (i < 114688) {         // att_w2 [128k,128n] -> [128n][128k]
        int j = i - 98304;
        int n = j >> 7, k = j & 127;
        v = att_w2[k*128 + n];
        hi = __float2bfloat16(v); lo = __float2bfloat16(v - __bfloat162float(hi));
        g_aw2b_hi[j] = hi; g_aw2b_lo[j] = lo;
    }
}

// ---------------- front-end tcgen05 GEMM + fused epilogues -------------------------
// MODE 0: nh = tanh(cat(pos,hidden) @ w1)           NTOT=128, KDIM=256 -> g_nh hi/lo
// MODE 1: beta = (sigmoid(nh@glu1_w+b) . w2)*(0.5+alpha)*mask   NTOT=512, KDIM=128
// MODE 2: alpha = sigmoid(tanh(hsw1 + hidden@att_w2) @ att_v)   NTOT=128, KDIM=128
#define F_OFF_TMEM 0
#define F_OFF_MBAR 8
#define F_OFF_AUX  64
#define F_OFF_AH   8192
#define F_OFF_AL   (8192 + 32768)
#define F_OFF_BH   73728
#define FRONT_IDESC(NHALF) ((1u<<4) | (1u<<7) | (1u<<10) | ((NHALF/8)<<17) | (8u<<24))

template<int NTOT, int KDIM, int MODE>
__global__ void __launch_bounds__(256, 1) k_mma_front(
    const float* __restrict__ pos_emb, const float* __restrict__ hidden,
    const float* __restrict__ glu1_b, const float* __restrict__ w2,
    const float* __restrict__ att_v, const int* __restrict__ mask)
{
    constexpr int NHALF = (NTOT > 256) ? 256 : NTOT;
    constexpr int NH  = NTOT / NHALF;
    constexpr int KCH = KDIM / 128;
#if HAS_TCGEN05
    constexpr int BBYTES = NHALF * 128 * 2;
    extern __shared__ char smem[];
    uint32_t sbase = smem_u32(smem);
    int tid = threadIdx.x, wid = tid >> 5, lane = tid & 31;
    int mtile = blockIdx.x;

    float* aux = (float*)(smem + F_OFF_AUX);
    if (MODE == 1) for (int i = tid; i < 512; i += 256) { aux[i] = glu1_b[i]; aux[512 + i] = w2[i]; }
    if (MODE == 2) for (int i = tid; i < 512; i += 256) aux[i] = att_v[i];

    if (tid == 0)
        asm volatile("mbarrier.init.shared.b64 [%0], 1;" :: "r"(sbase + F_OFF_MBAR) : "memory");
    if (wid == 4)
        asm volatile("tcgen05.alloc.cta_group::1.sync.aligned.shared::cta.b32 [%0], %1;"
                     :: "r"(sbase + F_OFF_TMEM), "r"((uint32_t)NTOT) : "memory");
    __syncthreads();
    uint32_t tmem;
    asm volatile("ld.shared.b32 %0, [%1];" : "=r"(tmem) : "r"(sbase + F_OFF_TMEM));

    int iter = 0;
    for (int kc = 0; kc < KCH; kc++) {
        // ---- stage A chunk [128m x 128k] hi/lo ----
        if (MODE == 1) {
            for (int i = tid; i < 128*16; i += 256) {
                int r = i >> 4, c8 = i & 15;
                uint32_t byte = (uint32_t)((c8 >> 3)*16 + (r >> 3))*1024u
                              + (uint32_t)(r & 7)*128u + (uint32_t)(c8 & 7)*16u;
                uint32_t sw = SWZ128(byte);
                int off = (mtile*128 + r)*DD + (c8 >> 3)*64 + (c8 & 7)*8;
                *(uint4*)(smem + F_OFF_AH + sw) = *(const uint4*)(g_nh_hi + off);
                *(uint4*)(smem + F_OFF_AL + sw) = *(const uint4*)(g_nh_lo + off);
            }
        } else {
            for (int i = tid; i < 128*16; i += 256) {
                int r = i >> 4, c8 = i & 15;
                int m = mtile*128 + r;
                int col = (c8 >> 3)*64 + (c8 & 7)*8;
                const float* src;
                if (MODE == 0) src = (kc == 0) ? (pos_emb + (m % LL)*DD + col)
                                               : (hidden + (size_t)m*DD + col);
                else           src = hidden + (size_t)m*DD + col;
                float f[8];
                *(float4*)f       = *(const float4*)src;
                *(float4*)(f + 4) = *(const float4*)(src + 4);
                __align__(16) ushort h[8], l[8];
                #pragma unroll
                for (int q = 0; q < 8; q++) { float rem; h[q] = bf_hi_us(f[q], rem); l[q] = bf_us(rem); }
                uint32_t byte = (uint32_t)((c8 >> 3)*16 + (r >> 3))*1024u
                              + (uint32_t)(r & 7)*128u + (uint32_t)(c8 & 7)*16u;
                uint32_t sw = SWZ128(byte);
                *(uint4*)(smem + F_OFF_AH + sw) = *(uint4*)h;
                *(uint4*)(smem + F_OFF_AL + sw) = *(uint4*)l;
            }
        }
        for (int h = 0; h < NH; h++) {
            // ---- stage B [NHALF n x 128 k] hi/lo ----
            const __nv_bfloat16 *bhsrc, *blsrc;
            if (MODE == 0)      { bhsrc = g_w1b_hi;  blsrc = g_w1b_lo;  }
            else if (MODE == 1) { bhsrc = g_glub_hi; blsrc = g_glub_lo; }
            else                { bhsrc = g_aw2b_hi; blsrc = g_aw2b_lo; }
            for (int i = tid; i < NHALF*16; i += 256) {
                int r = i >> 4, c8 = i & 15;
                int n = h*NHALF + r;
                int col = kc*128 + (c8 >> 3)*64 + (c8 & 7)*8;
                int off = n*KDIM + col;
                uint32_t byte = (uint32_t)((c8 >> 3)*(NHALF/8) + (r >> 3))*1024u
                              + (uint32_t)(r & 7)*128u + (uint32_t)(c8 & 7)*16u;
                uint32_t sw = SWZ128(byte);
                *(uint4*)(smem + F_OFF_BH + sw)          = *(const uint4*)(bhsrc + off);
                *(uint4*)(smem + F_OFF_BH + BBYTES + sw) = *(const uint4*)(blsrc + off);
            }
            __syncthreads();
            if (wid == 4 && elect1()) {
                asm volatile("fence.proxy.async.shared::cta;" ::: "memory");
                uint64_t dAh = MAKE_DESC(sbase + F_OFF_AH);
                uint64_t dAl = MAKE_DESC(sbase + F_OFF_AL);
                uint64_t dBh = MAKE_DESC(sbase + F_OFF_BH);
                uint64_t dBl = MAKE_DESC(sbase + F_OFF_BH + BBYTES);
                uint64_t ad[3] = { dAh, dAh, dAl };
                uint64_t bd[3] = { dBh, dBl, dBh };
                #pragma unroll
                for (int p = 0; p < 3; p++) {
                    #pragma unroll
                    for (int s = 0; s < 8; s++) {
                        uint64_t a = ad[p] + (uint64_t)((s >> 2)*1024 + (s & 3)*2);
                        uint64_t b = bd[p] + (uint64_t)((s >> 2)*(NHALF*8) + (s & 3)*2);
                        mma_f16_ss(tmem + h*NHALF, a, b, FRONT_IDESC(NHALF),
                                   !(kc == 0 && p == 0 && s == 0));
                    }
                }
                asm volatile(
                    "tcgen05.commit.cta_group::1.mbarrier::arrive::one.shared::cluster.b64 [%0];"
                    :: "r"(sbase + F_OFF_MBAR) : "memory");
            }
            MBAR_WAIT(sbase + F_OFF_MBAR, (uint32_t)(iter & 1));
            iter++;
        }
    }
    asm volatile("tcgen05.fence::after_thread_sync;" ::: "memory");

    // ---- fused epilogue (warps 0-3; lane = m-row of its subpartition) ----
    if (wid < 4) {
        int m = mtile*128 + wid*32 + lane;
        if (MODE == 0) {
            uint32_t* dsth = (uint32_t*)g_nh_hi + m*64;
            uint32_t* dstl = (uint32_t*)g_nh_lo + m*64;
            #pragma unroll 1
            for (int ch = 0; ch < 4; ch++) {
                uint32_t r[32];
                LDTM32(r, tmem + ch*32);
                asm volatile("tcgen05.wait::ld.sync.aligned;" ::: "memory");
                uint32_t hu[16], lu[16];
                #pragma unroll
                for (int j = 0; j < 16; j++) {
                    float v0 = tanhf(__uint_as_float(r[2*j]));
                    float v1 = tanhf(__uint_as_float(r[2*j + 1]));
                    float r0, r1;
                    ushort h0 = bf_hi_us(v0, r0), h1 = bf_hi_us(v1, r1);
                    hu[j] = ((uint32_t)h1 << 16) | h0;
                    lu[j] = ((uint32_t)bf_us(r1) << 16) | bf_us(r0);
                }
                #pragma unroll
                for (int q = 0; q < 4; q++) {
                    *(uint4*)(dsth + ch*16 + q*4) = make_uint4(hu[4*q], hu[4*q+1], hu[4*q+2], hu[4*q+3]);
                    *(uint4*)(dstl + ch*16 + q*4) = make_uint4(lu[4*q], lu[4*q+1], lu[4*q+2], lu[4*q+3]);
                }
            }
        } else if (MODE == 2) {
            float acc[4] = {};
            const float* hsrow = g_hsw1 + (m / LL)*DD;
            #pragma unroll 1
            for (int ch = 0; ch < 4; ch++) {
                uint32_t r[32];
                LDTM32(r, tmem + ch*32);
                asm volatile("tcgen05.wait::ld.sync.aligned;" ::: "memory");
                #pragma unroll
                for (int j = 0; j < 32; j++) {
                    int c = ch*32 + j;
                    float t = tanhf(__uint_as_float(r[j]) + hsrow[c]);
                    #pragma unroll
                    for (int k = 0; k < 4; k++) acc[k] += t * aux[c*4 + k];
                }
            }
            float4 al;
            al.x = sigmoidf(acc[0]); al.y = sigmoidf(acc[1]);
            al.z = sigmoidf(acc[2]); al.w = sigmoidf(acc[3]);
            *(float4*)(g_alpha + m*4) = al;
        } else { // MODE 1
            float acc[4] = {};
            #pragma unroll 1
            for (int ch = 0; ch < 16; ch++) {
                uint32_t r[32];
                LDTM32(r, tmem + ch*32);
                asm volatile("tcgen05.wait::ld.sync.aligned;" ::: "memory");
                int k = ch >> 2;
                float a = 0.f;
                #pragma unroll
                for (int j = 0; j < 32; j++) {
                    int c = ch*32 + j;
                    int d = c & 127;
                    float s = sigmoidf(__uint_as_float(r[j]) + aux[c]);
                    a += s * aux[512 + d*4 + k];
                }
                acc[k] += a;
            }
            float mk = (float)mask[m];
            float4 be;
            be.x = acc[0] * (0.5f + g_alpha[m*4+0]) * mk;
            be.y = acc[1] * (0.5f + g_alpha[m*4+1]) * mk;
            be.z = acc[2] * (0.5f + g_alpha[m*4+2]) * mk;
            be.w = acc[3] * (0.5f + g_alpha[m*4+3]) * mk;
            *(float4*)(g_beta + m*4) = be;
        }
    }
    __syncthreads();
    if (wid == 4)
        asm volatile("tcgen05.dealloc.cta_group::1.sync.aligned.b32 %0, %1;"
                     :: "r"(tmem), "r"((uint32_t)NTOT));
#else
    // ---------- correct (slow) fallback for non-'a' compile targets ----------
    int tid = threadIdx.x;
    if (tid >= 128) return;
    int m = blockIdx.x*128 + tid;
    if (MODE == 0) {
        for (int n = 0; n < 128; n++) {
            float acc = 0.f;
            for (int k = 0; k < 256; k++) {
                float a = (k < 128) ? pos_emb[(m % LL)*DD + k] : hidden[(size_t)m*DD + k - 128];
                float b = __bfloat162float(g_w1b_hi[n*256 + k]) + __bfloat162float(g_w1b_lo[n*256 + k]);
                acc += a * b;
            }
            float v = tanhf(acc);
            __nv_bfloat16 hb = __float2bfloat16(v);
            g_nh_hi[m*DD + n] = hb;
            g_nh_lo[m*DD + n] = __float2bfloat16(v - __bfloat162float(hb));
        }
    } else if (MODE == 2) {
        float acc[4] = {};
        for (int n = 0; n < 128; n++) {
            float x = 0.f;
            for (int k = 0; k < 128; k++)
                x += hidden[(size_t)m*DD + k] *
                     (__bfloat162float(g_aw2b_hi[n*128 + k]) + __bfloat162float(g_aw2b_lo[n*128 + k]));
            float t = tanhf(x + g_hsw1[(m / LL)*DD + n]);
            for (int k = 0; k < 4; k++) acc[k] += t * att_v[n*4 + k];
        }
        for (int k = 0; k < 4; k++) g_alpha[m*4 + k] = sigmoidf(acc[k]);
    } else {
        float acc[4] = {};
        for (int n = 0; n < 512; n++) {
            float x = 0.f;
            for (int k = 0; k < 128; k++) {
                float a = __bfloat162float(g_nh_hi[m*DD + k]) + __bfloat162float(g_nh_lo[m*DD + k]);
                x += a * (__bfloat162float(g_glub_hi[n*128 + k]) + __bfloat162float(g_glub_lo[n*128 + k]));
            }
            float s = sigmoidf(x + glu1_b[n]);
            acc[n >> 7] += s * w2[(n & 127)*4 + (n >> 7)];
        }
        float mk = (float)mask[m];
        for (int k = 0; k < 4; k++)
            g_beta[m*4 + k] = acc[k] * (0.5f + g_alpha[m*4 + k]) * mk;
    }
#endif
}

// ---------------- select -> bf16 hi/lo rows [m=b*4+k][d] ---------------------------
__global__ void k_select(const float* __restrict__ hidden)
{
    int b = blockIdx.x, t = threadIdx.x;   // t = d
    float acc[4] = {};
    for (int l = 0; l < LL; l++) {
        float h = hidden[(b*LL + l)*DD + t];
        float4 be = *(const float4*)(&g_beta[(b*LL + l)*4]);
        acc[0] += be.x*h; acc[1] += be.y*h; acc[2] += be.z*h; acc[3] += be.w*h;
    }
    #pragma unroll
    for (int k = 0; k < 4; k++) {
        float v = acc[k];
        __nv_bfloat16 hi = __float2bfloat16(v);
        __nv_bfloat16 lo = __float2bfloat16(v - __bfloat162float(hi));
        g_sel_hi[(b*4 + k)*DD + t] = hi;
        g_sel_lo[(b*4 + k)*DD + t] = lo;
    }
}

// ---------------- loss1 scalar -----------------------------------------------------
__global__ void k_loss(float* __restrict__ out_scalar)
{
    int b = threadIdx.x;
    float n2[4] = {};
    for (int l = 0; l < LL; l++) {
        float4 be = *(const float4*)(&g_beta[(b*LL + l)*4]);
        n2[0]+=be.x*be.x; n2[1]+=be.y*be.y; n2[2]+=be.z*be.z; n2[3]+=be.w*be.w;
    }
    float inv[4];
    #pragma unroll
    for (int k = 0; k < 4; k++) inv[k] = 1.0f / fmaxf(sqrtf(n2[k]), EPS_N);
    float G[6] = {};
    for (int l = 0; l < LL; l++) {
        float4 be = *(const float4*)(&g_beta[(b*LL + l)*4]);
        float v0=be.x*inv[0], v1=be.y*inv[1], v2=be.z*inv[2], v3=be.w*inv[3];
        G[0]+=v0*v1; G[1]+=v0*v2; G[2]+=v0*v3;
        G[3]+=v1*v2; G[4]+=v1*v3; G[5]+=v2*v3;
    }
    float sim = 0.f;
    #pragma unroll
    for (int i = 0; i < 6; i++) sim += fabsf(G[i]);
    sim *= (2.0f / (KK*(KK-1)));
    float lossb = sigmoidf(sim * g_lens[b]);
    __shared__ float red[BB];
    red[b] = lossb;  __syncthreads();
    for (int s = BB/2; s > 0; s >>= 1) {
        if (b < s) red[b] += red[b + s];
        __syncthreads();
    }
    if (b == 0) *out_scalar = red[0] * BETA_S;
}

// ---------------- emb: normalize rows + bf16 hi/lo split ---------------------------
__global__ void k_prep_emb(const float* __restrict__ emb)
{
    int w = threadIdx.x >> 5, lane = threadIdx.x & 31;
    int v = blockIdx.x*8 + w;
    if (v >= VM1) return;
    float4 x = *(const float4*)(emb + (size_t)(1 + v)*DD + lane*4);
    float s = x.x*x.x + x.y*x.y + x.z*x.z + x.w*x.w;
    #pragma unroll
    for (int o = 16; o > 0; o >>= 1) s += __shfl_xor_sync(0xffffffffu, s, o);
    float inv = 1.0f / fmaxf(sqrtf(s), EPS_N);
    float n[4] = {x.x*inv, x.y*inv, x.z*inv, x.w*inv};
    __nv_bfloat16 hi[4], lo[4];
    #pragma unroll
    for (int i = 0; i < 4; i++) {
        hi[i] = __float2bfloat16(n[i]);
        lo[i] = __float2bfloat16(n[i] - __bfloat162float(hi[i]));
    }
    *(uint64_t*)(&g_emb_hi[(size_t)v*DD + lane*4]) = *(uint64_t*)hi;
    *(uint64_t*)(&g_emb_lo[(size_t)v*DD + lane*4]) = *(uint64_t*)lo;
}

// ---------------- big GEMM: scores[k,b,v] + k-max ----------------------------------
#define TILE_N 256
#define MMA_IDESC ((1u<<4) | (1u<<7) | (1u<<10) | ((TILE_N/8)<<17) | ((128/16)<<24))

#define OFF_TMEM 0
#define OFF_MBAR 8
#define OFF_AH   1024
#define OFF_AL   (OFF_AH + 32768)
#define OFF_BH   (OFF_AL + 32768)
#define OFF_BL   (OFF_BH + 65536)
#define SMEM_TOT (OFF_BL + 65536)
#define OFF_STG  1024
#define OFF_MSTG (OFF_STG + 4*32*33*4)

__global__ void __launch_bounds__(256, 1) k_scores_mma(
        float* __restrict__ maxsc, float* __restrict__ scores)
{
#if HAS_TCGEN05
    extern __shared__ char smem[];
    uint32_t sbase = smem_u32(smem);
    int tid = threadIdx.x;
    int wid = tid >> 5, lane = tid & 31;
    int mtile = blockIdx.x;            // 0..7
    int vbase = blockIdx.y * TILE_N;

    if (tid == 0) {
        asm volatile("mbarrier.init.shared.b64 [%0], 1;" :: "r"(sbase + OFF_MBAR) : "memory");
    }
    if (wid == 4) {
        asm volatile("tcgen05.alloc.cta_group::1.sync.aligned.shared::cta.b32 [%0], %1;"
                     :: "r"(sbase + OFF_TMEM), "r"(256u) : "memory");
    }
    __syncthreads();
    uint32_t tmem;
    asm volatile("ld.shared.b32 %0, [%1];" : "=r"(tmem) : "r"(sbase + OFF_TMEM));

    {
        const __nv_bfloat16* srcs[2] = { g_sel_hi, g_sel_lo };
        uint32_t offs[2] = { OFF_AH, OFF_AL };
        #pragma unroll
        for (int h = 0; h < 2; h++) {
            for (int i = tid; i < 128*16; i += 256) {
                int r = i >> 4, c8 = i & 15;
                uint32_t byte = (uint32_t)((c8 >> 3)*16 + (r >> 3))*1024u
                              + (uint32_t)(r & 7)*128u + (uint32_t)(c8 & 7)*16u;
                uint4 val = *(const uint4*)(srcs[h] + (mtile*128 + r)*DD + (c8 & 7)*8 + (c8 >> 3)*64);
                *(uint4*)(smem + offs[h] + SWZ128(byte)) = val;
            }
        }
    }
    {
        const __nv_bfloat16* srcs[2] = { g_emb_hi, g_emb_lo };
        uint32_t offs[2] = { OFF_BH, OFF_BL };
        #pragma unroll
        for (int h = 0; h < 2; h++) {
            for (int i = tid; i < 256*16; i += 256) {
                int r = i >> 4, c8 = i & 15;
                int v = vbase + r; if (v > VM1 - 1) v = VM1 - 1;
                uint32_t byte = (uint32_t)((c8 >> 3)*32 + (r >> 3))*1024u
                              + (uint32_t)(r & 7)*128u + (uint32_t)(c8 & 7)*16u;
                uint4 val = *(const uint4*)(srcs[h] + (size_t)v*DD + (c8 & 7)*8 + (c8 >> 3)*64);
                *(uint4*)(smem + offs[h] + SWZ128(byte)) = val;
            }
        }
    }
    __syncthreads();

    if (wid == 4) {
        if (elect1()) {
            asm volatile("fence.proxy.async.shared::cta;" ::: "memory");
            uint64_t dAh = MAKE_DESC(sbase + OFF_AH);
            uint64_t dAl = MAKE_DESC(sbase + OFF_AL);
            uint64_t dBh = MAKE_DESC(sbase + OFF_BH);
            uint64_t dBl = MAKE_DESC(sbase + OFF_BL);
            uint64_t ad[3] = { dAh, dAh, dAl };
            uint64_t bd[3] = { dBh, dBl, dBh };
            #pragma unroll
            for (int p = 0; p < 3; p++) {
                #pragma unroll
                for (int s = 0; s < 8; s++) {
                    uint64_t a = ad[p] + (uint64_t)((s >> 2)*1024 + (s & 3)*2);
                    uint64_t b = bd[p] + (uint64_t)((s >> 2)*2048 + (s & 3)*2);
                    mma_f16_ss(tmem, a, b, MMA_IDESC, !(p == 0 && s == 0));
                }
            }
            asm volatile(
                "tcgen05.commit.cta_group::1.mbarrier::arrive::one.shared::cluster.b64 [%0];"
                :: "r"(sbase + OFF_MBAR) : "memory");
        }
    }
    __syncthreads();
    MBAR_WAIT(sbase + OFF_MBAR, 0u);
    asm volatile("tcgen05.fence::after_thread_sync;" ::: "memory");

    if (wid < 4) {
        float* stg  = (float*)(smem + OFF_STG  + wid*(32*33*4));
        float* mstg = (float*)(smem + OFF_MSTG + wid*(8*33*4));
        #pragma unroll 1
        for (int chunk = 0; chunk < TILE_N/32; chunk++) {
            uint32_t r[32];
            LDTM32(r, tmem + chunk*32);
            asm volatile("tcgen05.wait::ld.sync.aligned;" ::: "memory");

            #pragma unroll
            for (int c = 0; c < 32; c++) {
                float v = __uint_as_float(r[c]);
                stg[lane*33 + c] = v;
                float mx = v;
                mx = fmaxf(mx, __shfl_xor_sync(0xffffffffu, mx, 1));
                mx = fmaxf(mx, __shfl_xor_sync(0xffffffffu, mx, 2));
                if ((lane & 3) == 0) mstg[(lane >> 2)*33 + c] = mx;
            }
            __syncwarp();

            int v = vbase + chunk*32 + lane;
            if (v < VM1) {
                #pragma unroll 4
                for (int rr = 0; rr < 32; rr++) {
                    int m = wid*32 + rr;
                    int k = m & 3;
                    int b = mtile*32 + (m >> 2);
                    scores[((size_t)k*BB + b)*VM1 + v] = stg[rr*33 + lane];
                }
                #pragma unroll
                for (int rr = 0; rr < 8; rr++) {
                    int b = mtile*32 + wid*8 + rr;
                    maxsc[(size_t)b*VM1 + v] = mstg[rr*33 + lane];
                }
            }
            __syncwarp();
        }
    }
    __syncthreads();
    if (wid == 4) {
        asm volatile("tcgen05.dealloc.cta_group::1.sync.aligned.b32 %0, %1;"
                     :: "r"(tmem), "r"(256u));
    }
#else
    // ------- fp32 fallback (compiled for non-'a' targets; correct, not fast) -------
    extern __shared__ char smem[];
    float* Af = (float*)smem;
    float* Bf = (float*)(smem + 65536);
    int tid = threadIdx.x;
    int tc = tid & 15, tr = tid >> 4;
    int mtile = blockIdx.x;
    int vbase = blockIdx.y * TILE_N;

    for (int i = tid; i < 128*128; i += 256) {
        int r = i >> 7, d = i & 127;
        int row = mtile*128 + r;
        float v = __bfloat162float(g_sel_hi[row*DD + d]) + __bfloat162float(g_sel_lo[row*DD + d]);
        Af[d*128 + r] = v;
    }
    #pragma unroll 1
    for (int half = 0; half < 2; half++) {
        __syncthreads();
        for (int i = tid; i < 128*128; i += 256) {
            int r = i >> 7, d = i & 127;
            int v = vbase + half*128 + r; if (v > VM1 - 1) v = VM1 - 1;
            Bf[d*128 + r] = __bfloat162float(g_emb_hi[(size_t)v*DD + d])
                          + __bfloat162float(g_emb_lo[(size_t)v*DD + d]);
        }
        __syncthreads();
        float acc[8][8] = {};
        for (int kc = 0; kc < 128; kc++) {
            float4 a0 = *(float4*)(Af + kc*128 + tr*8);
            float4 a1 = *(float4*)(Af + kc*128 + tr*8 + 4);
            float aa[8] = {a0.x,a0.y,a0.z,a0.w,a1.x,a1.y,a1.z,a1.w};
            #pragma unroll
            for (int j = 0; j < 8; j++) {
                float bv = Bf[kc*128 + tc + 16*j];
                #pragma unroll
                for (int i = 0; i < 8; i++) acc[i][j] += aa[i]*bv;
            }
        }
        #pragma unroll
        for (int j = 0; j < 8; j++) {
            int v = vbase + half*128 + tc + 16*j;
            if (v < VM1) {
                float mx0 = -3.402823466e38f, mx1 = mx0;
                #pragma unroll
                for (int i = 0; i < 8; i++) {
                    int m = tr*8 + i;
                    int k = m & 3;
                    int b = mtile*32 + (m >> 2);
                    scores[((size_t)k*BB + b)*VM1 + v] = acc[i][j];
                    if (i < 4) mx0 = fmaxf(mx0, acc[i][j]);
                    else       mx1 = fmaxf(mx1, acc[i][j]);
                }
                maxsc[(size_t)(mtile*32 + tr*2 + 0)*VM1 + v] = mx0;
                maxsc[(size_t)(mtile*32 + tr*2 + 1)*VM1 + v] = mx1;
            }
        }
    }
#endif
}

// ---------------- launch ------------------------------------------------------------
extern "C" void kernel_launch(void* const* d_in, const int* in_sizes, int n_in,
                              void* d_out, int out_size)
{
    const float* hidden  = (const float*)d_in[0];
    const int*   mask    = (const int*)  d_in[1];
    const float* pos_emb = (const float*)d_in[2];
    const float* w1      = (const float*)d_in[3];
    const float* w2      = (const float*)d_in[4];
    const float* glu1_w  = (const float*)d_in[5];
    const float* glu1_b  = (const float*)d_in[6];
    const float* att_w1  = (const float*)d_in[7];
    const float* att_w2  = (const float*)d_in[8];
    const float* att_v   = (const float*)d_in[9];
    const float* emb     = (const float*)d_in[10];

    float* out    = (float*)d_out;
    float* maxsc  = out;                                   // [B, Vm1]
    float* scalar = out + (size_t)BB*VM1;                  // [1]
    float* scores = out + (size_t)BB*VM1 + 1;              // [K, B, Vm1]

    const int SMEM_F_SMALL = 73728 + 2*(128*128*2);   // 139264 (NHALF=128)
    const int SMEM_F_BIG   = 73728 + 2*(256*128*2);   // 204800 (NHALF=256)

    cudaFuncSetAttribute(k_scores_mma,
                         cudaFuncAttributeMaxDynamicSharedMemorySize, SMEM_TOT);
    cudaFuncSetAttribute(k_mma_front<128,256,0>,
                         cudaFuncAttributeMaxDynamicSharedMemorySize, SMEM_F_SMALL);
    cudaFuncSetAttribute(k_mma_front<128,128,2>,
                         cudaFuncAttributeMaxDynamicSharedMemorySize, SMEM_F_SMALL);
    cudaFuncSetAttribute(k_mma_front<512,128,1>,
                         cudaFuncAttributeMaxDynamicSharedMemorySize, SMEM_F_BIG);

    k_prep_w<<<448, 256>>>(w1, glu1_w, att_w2);
    k_prep_emb<<<(VM1 + 7)/8, 256>>>(emb);
    k_hs<<<BB, 128>>>(hidden, mask, att_w1);

    k_mma_front<128,256,0><<<100, 256, SMEM_F_SMALL>>>(pos_emb, hidden, glu1_b, w2, att_v, mask);
    k_mma_front<128,128,2><<<100, 256, SMEM_F_SMALL>>>(pos_emb, hidden, glu1_b, w2, att_v, mask);
    k_mma_front<512,128,1><<<100, 256, SMEM_F_BIG  >>>(pos_emb, hidden, glu1_b, w2, att_v, mask);

    k_select<<<BB, 128>>>(hidden);
    k_loss<<<1, BB>>>(scalar);

    k_scores_mma<<<dim3(8, (VM1 + TILE_N - 1)/TILE_N), 256, SMEM_TOT>>>(maxsc, scores);
}

// round 7
// speedup vs baseline: 2.3186x; 1.1590x over previous
#include <cuda_runtime.h>
#include <cuda_bf16.h>
#include <cstdint>

// Problem constants
#define BB   256
#define LL   50
#define DD   128
#define KK   4
#define VV   50000
#define VM1  49999
#define BL   (BB*LL)        // 12800
#define LEN_OPT 5
#define BETA_S 0.01f
#define EPS_N  1e-12f

// Arch-specific (sm_103a) feature gate: tcgen05 only exists on the 'a' target.
#if defined(__CUDA_ARCH__)
#  if defined(__CUDA_ARCH_FEAT_SM103_ALL) || defined(__CUDA_ARCH_FEAT_SM100_ALL) || \
      defined(__CUDA_ARCH_FEAT_SM101_ALL) || \
      (defined(__CUDA_ARCH_SPECIFIC__) && (__CUDA_ARCH_SPECIFIC__ >= 1000)) || \
      (defined(__CUDA_ARCH_FAMILY_SPECIFIC__) && (__CUDA_ARCH_FAMILY_SPECIFIC__ >= 1000))
#    define HAS_TCGEN05 1
#  else
#    define HAS_TCGEN05 0
#  endif
#else
#  define HAS_TCGEN05 0
#endif

// ---------------- scratch (static device globals; no allocation) ----------------
__device__ float g_hs   [BB*DD];
__device__ float g_hsw1 [BB*DD];
__device__ float g_lens [BB];
__device__ float g_beta [BL*KK];
__device__ float g_alpha[BL*KK];
__device__ __align__(16) __nv_bfloat16 g_nh_hi[BL*DD];       // tanh(cat@w1) split
__device__ __align__(16) __nv_bfloat16 g_nh_lo[BL*DD];
__device__ __align__(16) __nv_bfloat16 g_sel_hi[BB*KK*DD];   // select rows [m=b*4+k][d]
__device__ __align__(16) __nv_bfloat16 g_sel_lo[BB*KK*DD];
__device__ __align__(16) __nv_bfloat16 g_emb_hi[(size_t)VM1*DD]; // normalized emb rows
__device__ __align__(16) __nv_bfloat16 g_emb_lo[(size_t)VM1*DD];
// weights in B-operand layout [n][k], bf16 hi/lo
__device__ __align__(16) __nv_bfloat16 g_w1b_hi[128*256],  g_w1b_lo[128*256];
__device__ __align__(16) __nv_bfloat16 g_glub_hi[512*128], g_glub_lo[512*128];
__device__ __align__(16) __nv_bfloat16 g_aw2b_hi[128*128], g_aw2b_lo[128*128];

__device__ __forceinline__ float sigmoidf(float x){ return 1.0f/(1.0f+expf(-x)); }

__device__ __forceinline__ uint32_t smem_u32(const void* p) {
    uint32_t a;
    asm("{ .reg .u64 t; cvta.to.shared.u64 t, %1; cvt.u32.u64 %0, t; }" : "=r"(a) : "l"(p));
    return a;
}
#define SWZ128(x) ((x) ^ (((x) >> 3) & 0x70))

static constexpr uint64_t SMEM_DESC_BASE_SW128 =
    (uint64_t(2) << 61) | (uint64_t(1) << 46) | (uint64_t(64) << 32) | (uint64_t(1) << 16);
#define MAKE_DESC(addr) (SMEM_DESC_BASE_SW128 | ((uint64_t)((addr) >> 4) & 0x3FFF))

#if HAS_TCGEN05
__device__ __forceinline__ uint32_t elect1() {
    uint32_t p;
    asm volatile("{ .reg .pred p; elect.sync _|p, 0xFFFFFFFF; selp.b32 %0,1,0,p; }" : "=r"(p));
    return p;
}
__device__ __forceinline__ void mma_f16_ss(uint32_t d_tmem, uint64_t a_desc,
                                           uint64_t b_desc, uint32_t idesc, int en)
{
    asm volatile(
        "{\n\t.reg .pred p;\n\t"
        "setp.ne.u32 p, %4, 0;\n\t"
        "tcgen05.mma.cta_group::1.kind::f16 [%0], %1, %2, %3, {%5,%5,%5,%5}, p;\n\t}"
        :: "r"(d_tmem), "l"(a_desc), "l"(b_desc), "r"(idesc), "r"(en), "r"(0u)
        : "memory");
}
__device__ __forceinline__ void cp16(uint32_t dst, const void* src) {
    asm volatile("cp.async.cg.shared.global [%0], [%1], 16;" :: "r"(dst), "l"(src));
}
__device__ __forceinline__ void cp_commit() { asm volatile("cp.async.commit_group;" ::: "memory"); }
__device__ __forceinline__ void cp_wait0()  { asm volatile("cp.async.wait_group 0;" ::: "memory"); }
__device__ __forceinline__ void cp_wait1()  { asm volatile("cp.async.wait_group 1;" ::: "memory"); }
#define MBAR_WAIT(mbar, par) do {                                              \
    asm volatile(                                                              \
        "{\n\t.reg .pred P1;\n\t"                                              \
        "WL_%=:\n\t"                                                           \
        "mbarrier.try_wait.parity.acquire.cta.shared::cta.b64 P1, [%0], %1, 0x989680;\n\t" \
        "@P1 bra.uni WD_%=;\n\t"                                               \
        "bra.uni WL_%=;\n\t"                                                   \
        "WD_%=:\n\t}" :: "r"(mbar), "r"(par) : "memory");                      \
} while(0)
#define LDTM32(r, addr)                                                        \
    asm volatile(                                                              \
        "tcgen05.ld.sync.aligned.32x32b.x32.b32 "                              \
        "{%0,%1,%2,%3,%4,%5,%6,%7,%8,%9,%10,%11,%12,%13,%14,%15,"              \
        "%16,%17,%18,%19,%20,%21,%22,%23,%24,%25,%26,%27,%28,%29,%30,%31}, [%32];" \
        : "=r"(r[0]),"=r"(r[1]),"=r"(r[2]),"=r"(r[3]),"=r"(r[4]),"=r"(r[5]),"=r"(r[6]),"=r"(r[7]), \
          "=r"(r[8]),"=r"(r[9]),"=r"(r[10]),"=r"(r[11]),"=r"(r[12]),"=r"(r[13]),"=r"(r[14]),"=r"(r[15]), \
          "=r"(r[16]),"=r"(r[17]),"=r"(r[18]),"=r"(r[19]),"=r"(r[20]),"=r"(r[21]),"=r"(r[22]),"=r"(r[23]), \
          "=r"(r[24]),"=r"(r[25]),"=r"(r[26]),"=r"(r[27]),"=r"(r[28]),"=r"(r[29]),"=r"(r[30]),"=r"(r[31]) \
        : "r"(addr))
#endif

__device__ __forceinline__ ushort bf_hi_us(float v, float& rem) {
    __nv_bfloat16 hb = __float2bfloat16(v);
    rem = v - __bfloat162float(hb);
    return *reinterpret_cast<ushort*>(&hb);
}
__device__ __forceinline__ ushort bf_us(float v) {
    __nv_bfloat16 b = __float2bfloat16(v);
    return *reinterpret_cast<ushort*>(&b);
}

// ---------------- kernel 1: masked mean hs, lens, hs@att_w1 ----------------
__global__ void k_hs(const float* __restrict__ hidden, const int* __restrict__ mask,
                     const float* __restrict__ att_w1)
{
    int b = blockIdx.x, t = threadIdx.x;
    __shared__ float hs_sm[DD];
    float acc = 0.f, sm = 0.f;
    for (int l = 0; l < LL; l++) {
        float mk = (float)mask[b*LL + l];
        sm  += mk;
        acc += hidden[(b*LL + l)*DD + t] * mk;
    }
    float hsv = acc / sm;
    hs_sm[t] = hsv;
    g_hs[b*DD + t] = hsv;
    if (t == 0) g_lens[b] = sm - (float)LEN_OPT;
    __syncthreads();
    float a2 = 0.f;
    #pragma unroll 8
    for (int e = 0; e < DD; e++) a2 += hs_sm[e] * att_w1[e*DD + t];
    g_hsw1[b*DD + t] = a2;
}

// ---------------- weight prep: transpose + bf16 hi/lo split ------------------------
__global__ void k_prep_w(const float* __restrict__ w1, const float* __restrict__ glu1_w,
                         const float* __restrict__ att_w2)
{
    int i = blockIdx.x*256 + threadIdx.x;
    float v; __nv_bfloat16 hi, lo;
    if (i < 32768) {                 // w1 [256k,128n] -> [128n][256k]
        int n = i >> 8, k = i & 255;
        v = w1[k*128 + n];
        hi = __float2bfloat16(v); lo = __float2bfloat16(v - __bfloat162float(hi));
        g_w1b_hi[i] = hi; g_w1b_lo[i] = lo;
    } else if (i < 32768 + 65536) {  // glu1_w [128k,512n] -> [512n][128k]
        int j = i - 32768;
        int n = j >> 7, k = j & 127;
        v = glu1_w[k*512 + n];
        hi = __float2bfloat16(v); lo = __float2bfloat16(v - __bfloat162float(hi));
        g_glub_hi[j] = hi; g_glub_lo[j] = lo;
    } else if (i < 114688) {         // att_w2 [128k,128n] -> [128n][128k]
        int j = i - 98304;
        int n = j >> 7, k = j & 127;
        v = att_w2[k*128 + n];
        hi = __float2bfloat16(v); lo = __float2bfloat16(v - __bfloat162float(hi));
        g_aw2b_hi[j] = hi; g_aw2b_lo[j] = lo;
    }
}

// ---------------- front-end tcgen05 GEMM + fused epilogues -------------------------
#define F_OFF_TMEM 0
#define F_OFF_MBAR 8
#define F_OFF_AUX  64
#define F_OFF_AH   8192
#define F_OFF_AL   (8192 + 32768)
#define F_OFF_BH   73728
#define FRONT_IDESC(NHALF) ((1u<<4) | (1u<<7) | (1u<<10) | ((NHALF/8)<<17) | (8u<<24))

template<int NTOT, int KDIM, int MODE>
__global__ void __launch_bounds__(256, 1) k_mma_front(
    const float* __restrict__ pos_emb, const float* __restrict__ hidden,
    const float* __restrict__ glu1_b, const float* __restrict__ w2,
    const float* __restrict__ att_v, const int* __restrict__ mask)
{
    constexpr int NHALF = (NTOT > 256) ? 256 : NTOT;
    constexpr int NH  = NTOT / NHALF;
    constexpr int KCH = KDIM / 128;
#if HAS_TCGEN05
    constexpr int BBYTES = NHALF * 128 * 2;
    extern __shared__ char smem[];
    uint32_t sbase = smem_u32(smem);
    int tid = threadIdx.x, wid = tid >> 5, lane = tid & 31;
    int mtile = blockIdx.x;

    float* aux = (float*)(smem + F_OFF_AUX);
    if (MODE == 1) for (int i = tid; i < 512; i += 256) { aux[i] = glu1_b[i]; aux[512 + i] = w2[i]; }
    if (MODE == 2) for (int i = tid; i < 512; i += 256) aux[i] = att_v[i];

    if (tid == 0)
        asm volatile("mbarrier.init.shared.b64 [%0], 1;" :: "r"(sbase + F_OFF_MBAR) : "memory");
    if (wid == 4)
        asm volatile("tcgen05.alloc.cta_group::1.sync.aligned.shared::cta.b32 [%0], %1;"
                     :: "r"(sbase + F_OFF_TMEM), "r"((uint32_t)NTOT) : "memory");
    __syncthreads();
    uint32_t tmem;
    asm volatile("ld.shared.b32 %0, [%1];" : "=r"(tmem) : "r"(sbase + F_OFF_TMEM));

    int iter = 0;
    for (int kc = 0; kc < KCH; kc++) {
        // ---- stage A chunk [128m x 128k] hi/lo ----
        if (MODE == 1) {
            for (int i = tid; i < 128*16; i += 256) {
                int r = i >> 4, c8 = i & 15;
                uint32_t byte = (uint32_t)((c8 >> 3)*16 + (r >> 3))*1024u
                              + (uint32_t)(r & 7)*128u + (uint32_t)(c8 & 7)*16u;
                uint32_t sw = SWZ128(byte);
                int off = (mtile*128 + r)*DD + (c8 >> 3)*64 + (c8 & 7)*8;
                *(uint4*)(smem + F_OFF_AH + sw) = *(const uint4*)(g_nh_hi + off);
                *(uint4*)(smem + F_OFF_AL + sw) = *(const uint4*)(g_nh_lo + off);
            }
        } else {
            for (int i = tid; i < 128*16; i += 256) {
                int r = i >> 4, c8 = i & 15;
                int m = mtile*128 + r;
                int col = (c8 >> 3)*64 + (c8 & 7)*8;
                const float* src;
                if (MODE == 0) src = (kc == 0) ? (pos_emb + (m % LL)*DD + col)
                                               : (hidden + (size_t)m*DD + col);
                else           src = hidden + (size_t)m*DD + col;
                float f[8];
                *(float4*)f       = *(const float4*)src;
                *(float4*)(f + 4) = *(const float4*)(src + 4);
                __align__(16) ushort h[8], l[8];
                #pragma unroll
                for (int q = 0; q < 8; q++) { float rem; h[q] = bf_hi_us(f[q], rem); l[q] = bf_us(rem); }
                uint32_t byte = (uint32_t)((c8 >> 3)*16 + (r >> 3))*1024u
                              + (uint32_t)(r & 7)*128u + (uint32_t)(c8 & 7)*16u;
                uint32_t sw = SWZ128(byte);
                *(uint4*)(smem + F_OFF_AH + sw) = *(uint4*)h;
                *(uint4*)(smem + F_OFF_AL + sw) = *(uint4*)l;
            }
        }
        for (int h = 0; h < NH; h++) {
            const __nv_bfloat16 *bhsrc, *blsrc;
            if (MODE == 0)      { bhsrc = g_w1b_hi;  blsrc = g_w1b_lo;  }
            else if (MODE == 1) { bhsrc = g_glub_hi; blsrc = g_glub_lo; }
            else                { bhsrc = g_aw2b_hi; blsrc = g_aw2b_lo; }
            for (int i = tid; i < NHALF*16; i += 256) {
                int r = i >> 4, c8 = i & 15;
                int n = h*NHALF + r;
                int col = kc*128 + (c8 >> 3)*64 + (c8 & 7)*8;
                int off = n*KDIM + col;
                uint32_t byte = (uint32_t)((c8 >> 3)*(NHALF/8) + (r >> 3))*1024u
                              + (uint32_t)(r & 7)*128u + (uint32_t)(c8 & 7)*16u;
                uint32_t sw = SWZ128(byte);
                *(uint4*)(smem + F_OFF_BH + sw)          = *(const uint4*)(bhsrc + off);
                *(uint4*)(smem + F_OFF_BH + BBYTES + sw) = *(const uint4*)(blsrc + off);
            }
            __syncthreads();
            if (wid == 4 && elect1()) {
                asm volatile("fence.proxy.async.shared::cta;" ::: "memory");
                uint64_t dAh = MAKE_DESC(sbase + F_OFF_AH);
                uint64_t dAl = MAKE_DESC(sbase + F_OFF_AL);
                uint64_t dBh = MAKE_DESC(sbase + F_OFF_BH);
                uint64_t dBl = MAKE_DESC(sbase + F_OFF_BH + BBYTES);
                uint64_t ad[3] = { dAh, dAh, dAl };
                uint64_t bd[3] = { dBh, dBl, dBh };
                #pragma unroll
                for (int p = 0; p < 3; p++) {
                    #pragma unroll
                    for (int s = 0; s < 8; s++) {
                        uint64_t a = ad[p] + (uint64_t)((s >> 2)*1024 + (s & 3)*2);
                        uint64_t b = bd[p] + (uint64_t)((s >> 2)*(NHALF*8) + (s & 3)*2);
                        mma_f16_ss(tmem + h*NHALF, a, b, FRONT_IDESC(NHALF),
                                   !(kc == 0 && p == 0 && s == 0));
                    }
                }
                asm volatile(
                    "tcgen05.commit.cta_group::1.mbarrier::arrive::one.shared::cluster.b64 [%0];"
                    :: "r"(sbase + F_OFF_MBAR) : "memory");
            }
            MBAR_WAIT(sbase + F_OFF_MBAR, (uint32_t)(iter & 1));
            iter++;
        }
    }
    asm volatile("tcgen05.fence::after_thread_sync;" ::: "memory");

    // ---- fused epilogue (warps 0-3; lane = m-row of its subpartition) ----
    if (wid < 4) {
        int m = mtile*128 + wid*32 + lane;
        if (MODE == 0) {
            uint32_t* dsth = (uint32_t*)g_nh_hi + m*64;
            uint32_t* dstl = (uint32_t*)g_nh_lo + m*64;
            #pragma unroll 1
            for (int ch = 0; ch < 4; ch++) {
                uint32_t r[32];
                LDTM32(r, tmem + ch*32);
                asm volatile("tcgen05.wait::ld.sync.aligned;" ::: "memory");
                uint32_t hu[16], lu[16];
                #pragma unroll
                for (int j = 0; j < 16; j++) {
                    float v0 = tanhf(__uint_as_float(r[2*j]));
                    float v1 = tanhf(__uint_as_float(r[2*j + 1]));
                    float r0, r1;
                    ushort h0 = bf_hi_us(v0, r0), h1 = bf_hi_us(v1, r1);
                    hu[j] = ((uint32_t)h1 << 16) | h0;
                    lu[j] = ((uint32_t)bf_us(r1) << 16) | bf_us(r0);
                }
                #pragma unroll
                for (int q = 0; q < 4; q++) {
                    *(uint4*)(dsth + ch*16 + q*4) = make_uint4(hu[4*q], hu[4*q+1], hu[4*q+2], hu[4*q+3]);
                    *(uint4*)(dstl + ch*16 + q*4) = make_uint4(lu[4*q], lu[4*q+1], lu[4*q+2], lu[4*q+3]);
                }
            }
        } else if (MODE == 2) {
            float acc[4] = {};
            const float* hsrow = g_hsw1 + (m / LL)*DD;
            #pragma unroll 1
            for (int ch = 0; ch < 4; ch++) {
                uint32_t r[32];
                LDTM32(r, tmem + ch*32);
                asm volatile("tcgen05.wait::ld.sync.aligned;" ::: "memory");
                #pragma unroll
                for (int j = 0; j < 32; j++) {
                    int c = ch*32 + j;
                    float t = tanhf(__uint_as_float(r[j]) + hsrow[c]);
                    #pragma unroll
                    for (int k = 0; k < 4; k++) acc[k] += t * aux[c*4 + k];
                }
            }
            float4 al;
            al.x = sigmoidf(acc[0]); al.y = sigmoidf(acc[1]);
            al.z = sigmoidf(acc[2]); al.w = sigmoidf(acc[3]);
            *(float4*)(g_alpha + m*4) = al;
        } else { // MODE 1
            float acc[4] = {};
            #pragma unroll 1
            for (int ch = 0; ch < 16; ch++) {
                uint32_t r[32];
                LDTM32(r, tmem + ch*32);
                asm volatile("tcgen05.wait::ld.sync.aligned;" ::: "memory");
                int k = ch >> 2;
                float a = 0.f;
                #pragma unroll
                for (int j = 0; j < 32; j++) {
                    int c = ch*32 + j;
                    int d = c & 127;
                    float s = sigmoidf(__uint_as_float(r[j]) + aux[c]);
                    a += s * aux[512 + d*4 + k];
                }
                acc[k] += a;
            }
            float mk = (float)mask[m];
            float4 be;
            be.x = acc[0] * (0.5f + g_alpha[m*4+0]) * mk;
            be.y = acc[1] * (0.5f + g_alpha[m*4+1]) * mk;
            be.z = acc[2] * (0.5f + g_alpha[m*4+2]) * mk;
            be.w = acc[3] * (0.5f + g_alpha[m*4+3]) * mk;
            *(float4*)(g_beta + m*4) = be;
        }
    }
    __syncthreads();
    if (wid == 4)
        asm volatile("tcgen05.dealloc.cta_group::1.sync.aligned.b32 %0, %1;"
                     :: "r"(tmem), "r"((uint32_t)NTOT));
#else
    // ---------- correct (slow) fallback for non-'a' compile targets ----------
    int tid = threadIdx.x;
    if (tid >= 128) return;
    int m = blockIdx.x*128 + tid;
    if (MODE == 0) {
        for (int n = 0; n < 128; n++) {
            float acc = 0.f;
            for (int k = 0; k < 256; k++) {
                float a = (k < 128) ? pos_emb[(m % LL)*DD + k] : hidden[(size_t)m*DD + k - 128];
                float b = __bfloat162float(g_w1b_hi[n*256 + k]) + __bfloat162float(g_w1b_lo[n*256 + k]);
                acc += a * b;
            }
            float v = tanhf(acc);
            __nv_bfloat16 hb = __float2bfloat16(v);
            g_nh_hi[m*DD + n] = hb;
            g_nh_lo[m*DD + n] = __float2bfloat16(v - __bfloat162float(hb));
        }
    } else if (MODE == 2) {
        float acc[4] = {};
        for (int n = 0; n < 128; n++) {
            float x = 0.f;
            for (int k = 0; k < 128; k++)
                x += hidden[(size_t)m*DD + k] *
                     (__bfloat162float(g_aw2b_hi[n*128 + k]) + __bfloat162float(g_aw2b_lo[n*128 + k]));
            float t = tanhf(x + g_hsw1[(m / LL)*DD + n]);
            for (int k = 0; k < 4; k++) acc[k] += t * att_v[n*4 + k];
        }
        for (int k = 0; k < 4; k++) g_alpha[m*4 + k] = sigmoidf(acc[k]);
    } else {
        float acc[4] = {};
        for (int n = 0; n < 512; n++) {
            float x = 0.f;
            for (int k = 0; k < 128; k++) {
                float a = __bfloat162float(g_nh_hi[m*DD + k]) + __bfloat162float(g_nh_lo[m*DD + k]);
                x += a * (__bfloat162float(g_glub_hi[n*128 + k]) + __bfloat162float(g_glub_lo[n*128 + k]));
            }
            float s = sigmoidf(x + glu1_b[n]);
            acc[n >> 7] += s * w2[(n & 127)*4 + (n >> 7)];
        }
        float mk = (float)mask[m];
        for (int k = 0; k < 4; k++)
            g_beta[m*4 + k] = acc[k] * (0.5f + g_alpha[m*4 + k]) * mk;
    }
#endif
}

// ---------------- select -> bf16 hi/lo rows [m=b*4+k][d] ---------------------------
__global__ void k_select(const float* __restrict__ hidden)
{
    int b = blockIdx.x, t = threadIdx.x;   // t = d
    float acc[4] = {};
    for (int l = 0; l < LL; l++) {
        float h = hidden[(b*LL + l)*DD + t];
        float4 be = *(const float4*)(&g_beta[(b*LL + l)*4]);
        acc[0] += be.x*h; acc[1] += be.y*h; acc[2] += be.z*h; acc[3] += be.w*h;
    }
    #pragma unroll
    for (int k = 0; k < 4; k++) {
        float v = acc[k];
        __nv_bfloat16 hi = __float2bfloat16(v);
        __nv_bfloat16 lo = __float2bfloat16(v - __bfloat162float(hi));
        g_sel_hi[(b*4 + k)*DD + t] = hi;
        g_sel_lo[(b*4 + k)*DD + t] = lo;
    }
}

// ---------------- loss1 scalar -----------------------------------------------------
__global__ void k_loss(float* __restrict__ out_scalar)
{
    int b = threadIdx.x;
    float n2[4] = {};
    for (int l = 0; l < LL; l++) {
        float4 be = *(const float4*)(&g_beta[(b*LL + l)*4]);
        n2[0]+=be.x*be.x; n2[1]+=be.y*be.y; n2[2]+=be.z*be.z; n2[3]+=be.w*be.w;
    }
    float inv[4];
    #pragma unroll
    for (int k = 0; k < 4; k++) inv[k] = 1.0f / fmaxf(sqrtf(n2[k]), EPS_N);
    float G[6] = {};
    for (int l = 0; l < LL; l++) {
        float4 be = *(const float4*)(&g_beta[(b*LL + l)*4]);
        float v0=be.x*inv[0], v1=be.y*inv[1], v2=be.z*inv[2], v3=be.w*inv[3];
        G[0]+=v0*v1; G[1]+=v0*v2; G[2]+=v0*v3;
        G[3]+=v1*v2; G[4]+=v1*v3; G[5]+=v2*v3;
    }
    float sim = 0.f;
    #pragma unroll
    for (int i = 0; i < 6; i++) sim += fabsf(G[i]);
    sim *= (2.0f / (KK*(KK-1)));
    float lossb = sigmoidf(sim * g_lens[b]);
    __shared__ float red[BB];
    red[b] = lossb;  __syncthreads();
    for (int s = BB/2; s > 0; s >>= 1) {
        if (b < s) red[b] += red[b + s];
        __syncthreads();
    }
    if (b == 0) *out_scalar = red[0] * BETA_S;
}

// ---------------- emb: normalize rows + bf16 hi/lo split ---------------------------
__global__ void k_prep_emb(const float* __restrict__ emb)
{
    int w = threadIdx.x >> 5, lane = threadIdx.x & 31;
    int v = blockIdx.x*8 + w;
    if (v >= VM1) return;
    float4 x = *(const float4*)(emb + (size_t)(1 + v)*DD + lane*4);
    float s = x.x*x.x + x.y*x.y + x.z*x.z + x.w*x.w;
    #pragma unroll
    for (int o = 16; o > 0; o >>= 1) s += __shfl_xor_sync(0xffffffffu, s, o);
    float inv = 1.0f / fmaxf(sqrtf(s), EPS_N);
    float n[4] = {x.x*inv, x.y*inv, x.z*inv, x.w*inv};
    __nv_bfloat16 hi[4], lo[4];
    #pragma unroll
    for (int i = 0; i < 4; i++) {
        hi[i] = __float2bfloat16(n[i]);
        lo[i] = __float2bfloat16(n[i] - __bfloat162float(hi[i]));
    }
    *(uint64_t*)(&g_emb_hi[(size_t)v*DD + lane*4]) = *(uint64_t*)hi;
    *(uint64_t*)(&g_emb_lo[(size_t)v*DD + lane*4]) = *(uint64_t*)lo;
}

// ---------------- big GEMM: pipelined scores[k,b,v] + k-max ------------------------
// grid (8 mtiles, 98 vgroups); each CTA: A once + up to 4 N-tiles of 128 v.
// warps 0-3 epilogue, warp 4 MMA issue, warps 5-7 cp.async B prefetch.
// TMEM: 2 accumulator halves (128 cols each) for tile-level double buffering.
#define N_VTILES 391
#define S_IDESC ((1u<<4) | (1u<<7) | (1u<<10) | ((128/8)<<17) | (8u<<24))
#define S_OFF_TMEM  0
#define S_OFF_MBAR0 8
#define S_OFF_MBAR1 16
#define S_OFF_A     1024
#define S_OFF_B0    (1024 + 65536)      // 66560
#define S_OFF_B1    (66560 + 65536)     // 132096
#define S_OFF_STG   (132096 + 65536)    // 197632
#define S_OFF_MSTG  (197632 + 4*32*33*4)// 214528
#define S_SMEM_TOT  (214528 + 4*8*33*4) // 218752

#if HAS_TCGEN05
__device__ __forceinline__ void s_load_b_async(uint32_t bufbase, int vtile, int wt)
{
    int vbase = vtile * 128;
    for (int i = wt; i < 4096; i += 96) {
        int half = i >> 11, rem = i & 2047;
        int r = rem >> 4, c8 = rem & 15;
        int v = vbase + r; if (v > VM1 - 1) v = VM1 - 1;
        const __nv_bfloat16* src = (half ? g_emb_lo : g_emb_hi)
                                 + (size_t)v*DD + (c8 >> 3)*64 + (c8 & 7)*8;
        uint32_t byte = (uint32_t)((c8 >> 3)*16 + (r >> 3))*1024u
                      + (uint32_t)(r & 7)*128u + (uint32_t)(c8 & 7)*16u;
        cp16(bufbase + half*32768u + SWZ128(byte), src);
    }
    cp_commit();
}
__device__ __forceinline__ void s_issue_mma(uint32_t tmem_d, uint32_t sbase,
                                            uint32_t bufoff, uint32_t mbar)
{
    asm volatile("fence.proxy.async.shared::cta;" ::: "memory");
    uint64_t dAh = MAKE_DESC(sbase + S_OFF_A);
    uint64_t dAl = MAKE_DESC(sbase + S_OFF_A + 32768);
    uint64_t dBh = MAKE_DESC(sbase + bufoff);
    uint64_t dBl = MAKE_DESC(sbase + bufoff + 32768);
    uint64_t ad[3] = { dAh, dAh, dAl };
    uint64_t bd[3] = { dBh, dBl, dBh };
    #pragma unroll
    for (int p = 0; p < 3; p++) {
        #pragma unroll
        for (int s = 0; s < 8; s++) {
            uint64_t a = ad[p] + (uint64_t)((s >> 2)*1024 + (s & 3)*2);
            uint64_t b = bd[p] + (uint64_t)((s >> 2)*1024 + (s & 3)*2);
            mma_f16_ss(tmem_d, a, b, S_IDESC, !(p == 0 && s == 0));
        }
    }
    asm volatile(
        "tcgen05.commit.cta_group::1.mbarrier::arrive::one.shared::cluster.b64 [%0];"
        :: "r"(mbar) : "memory");
}
#endif

__global__ void __launch_bounds__(256, 1) k_scores_mma(
        float* __restrict__ maxsc, float* __restrict__ scores)
{
#if HAS_TCGEN05
    extern __shared__ char smem[];
    uint32_t sbase = smem_u32(smem);
    int tid = threadIdx.x, wid = tid >> 5, lane = tid & 31;
    int mtile = blockIdx.x;
    int t0 = blockIdx.y * 4;
    int NT = N_VTILES - t0; if (NT > 4) NT = 4;   // always >= 3

    if (tid == 0) {
        asm volatile("mbarrier.init.shared.b64 [%0], 1;" :: "r"(sbase + S_OFF_MBAR0) : "memory");
        asm volatile("mbarrier.init.shared.b64 [%0], 1;" :: "r"(sbase + S_OFF_MBAR1) : "memory");
    }
    if (wid == 4)
        asm volatile("tcgen05.alloc.cta_group::1.sync.aligned.shared::cta.b32 [%0], %1;"
                     :: "r"(sbase + S_OFF_TMEM), "r"(256u) : "memory");
    __syncthreads();
    uint32_t tmem;
    asm volatile("ld.shared.b32 %0, [%1];" : "=r"(tmem) : "r"(sbase + S_OFF_TMEM));

    // ---- prologue: warps 0-4 stage A; warps 5-7 prefetch B0, B1 ----
    if (tid < 160) {
        for (int i = tid; i < 128*16; i += 160) {
            int r = i >> 4, c8 = i & 15;
            uint32_t byte = (uint32_t)((c8 >> 3)*16 + (r >> 3))*1024u
                          + (uint32_t)(r & 7)*128u + (uint32_t)(c8 & 7)*16u;
            uint32_t sw = SWZ128(byte);
            int off = (mtile*128 + r)*DD + (c8 >> 3)*64 + (c8 & 7)*8;
            *(uint4*)(smem + S_OFF_A + sw)         = *(const uint4*)(g_sel_hi + off);
            *(uint4*)(smem + S_OFF_A + 32768 + sw) = *(const uint4*)(g_sel_lo + off);
        }
    } else {
        int wt = tid - 160;
        s_load_b_async(sbase + S_OFF_B0, t0 + 0, wt);
        s_load_b_async(sbase + S_OFF_B1, t0 + 1, wt);
        cp_wait1();   // B0 arrived
    }
    __syncthreads();
    if (wid == 4 && elect1())
        s_issue_mma(tmem, sbase, S_OFF_B0, sbase + S_OFF_MBAR0);

    // ---- steady-state pipeline ----
    for (int t = 0; t < NT; t++) {
        if (tid >= 160 && t + 1 < NT) cp_wait0();                 // B(t+1) arrived
        MBAR_WAIT(sbase + ((t & 1) ? S_OFF_MBAR1 : S_OFF_MBAR0), (uint32_t)((t >> 1) & 1));
        asm volatile("tcgen05.fence::after_thread_sync;" ::: "memory");
        __syncthreads();                                          // epilogue(t-1) done too

        if (t + 1 < NT && wid == 4 && elect1())
            s_issue_mma(tmem + (((t + 1) & 1) << 7), sbase,
                        ((t + 1) & 1) ? S_OFF_B1 : S_OFF_B0,
                        sbase + (((t + 1) & 1) ? S_OFF_MBAR1 : S_OFF_MBAR0));
        if (t + 2 < NT && tid >= 160)
            s_load_b_async(sbase + ((t & 1) ? S_OFF_B1 : S_OFF_B0), t0 + t + 2, tid - 160);

        if (wid < 4) {
            uint32_t tbase = tmem + ((t & 1) << 7);
            int vb = (t0 + t)*128;
            float* stg  = (float*)(smem + S_OFF_STG  + wid*(32*33*4));
            float* mstg = (float*)(smem + S_OFF_MSTG + wid*(8*33*4));
            #pragma unroll 1
            for (int chunk = 0; chunk < 4; chunk++) {
                uint32_t r[32];
                LDTM32(r, tbase + chunk*32);
                asm volatile("tcgen05.wait::ld.sync.aligned;" ::: "memory");
                #pragma unroll
                for (int c = 0; c < 32; c++) {
                    float v = __uint_as_float(r[c]);
                    stg[lane*33 + c] = v;
                    float mx = v;
                    mx = fmaxf(mx, __shfl_xor_sync(0xffffffffu, mx, 1));
                    mx = fmaxf(mx, __shfl_xor_sync(0xffffffffu, mx, 2));
                    if ((lane & 3) == 0) mstg[(lane >> 2)*33 + c] = mx;
                }
                __syncwarp();
                int v = vb + chunk*32 + lane;
                if (v < VM1) {
                    #pragma unroll 4
                    for (int rr = 0; rr < 32; rr++) {
                        int m = wid*32 + rr;
                        int k = m & 3;
                        int b = mtile*32 + (m >> 2);
                        scores[((size_t)k*BB + b)*VM1 + v] = stg[rr*33 + lane];
                    }
                    #pragma unroll
                    for (int rr = 0; rr < 8; rr++) {
                        int b = mtile*32 + wid*8 + rr;
                        maxsc[(size_t)b*VM1 + v] = mstg[rr*33 + lane];
                    }
                }
                __syncwarp();
            }
        }
    }
    __syncthreads();
    if (wid == 4)
        asm volatile("tcgen05.dealloc.cta_group::1.sync.aligned.b32 %0, %1;"
                     :: "r"(tmem), "r"(256u));
#else
    // ------- correct (slow) fallback for non-'a' targets -------
    int tid = threadIdx.x;
    int mtile = blockIdx.x;
    int t0 = blockIdx.y * 4;
    int NT = N_VTILES - t0; if (NT > 4) NT = 4;
    for (int t = 0; t < NT; t++) {
        int vbase = (t0 + t)*128;
        for (int p = tid; p < 32*128; p += 256) {
            int bl = p >> 7, vv = vbase + (p & 127);
            if (vv >= VM1) continue;
            int b = mtile*32 + bl;
            float mx = -3.402823466e38f;
            for (int k = 0; k < 4; k++) {
                int m = (b*4 + k);
                float acc = 0.f;
                for (int d = 0; d < DD; d++) {
                    float a = __bfloat162float(g_sel_hi[m*DD + d]) + __bfloat162float(g_sel_lo[m*DD + d]);
                    float e = __bfloat162float(g_emb_hi[(size_t)vv*DD + d]) + __bfloat162float(g_emb_lo[(size_t)vv*DD + d]);
                    acc += a * e;
                }
                scores[((size_t)k*BB + b)*VM1 + vv] = acc;
                mx = fmaxf(mx, acc);
            }
            maxsc[(size_t)b*VM1 + vv] = mx;
        }
    }
#endif
}

// ---------------- launch ------------------------------------------------------------
extern "C" void kernel_launch(void* const* d_in, const int* in_sizes, int n_in,
                              void* d_out, int out_size)
{
    const float* hidden  = (const float*)d_in[0];
    const int*   mask    = (const int*)  d_in[1];
    const float* pos_emb = (const float*)d_in[2];
    const float* w1      = (const float*)d_in[3];
    const float* w2      = (const float*)d_in[4];
    const float* glu1_w  = (const float*)d_in[5];
    const float* glu1_b  = (const float*)d_in[6];
    const float* att_w1  = (const float*)d_in[7];
    const float* att_w2  = (const float*)d_in[8];
    const float* att_v   = (const float*)d_in[9];
    const float* emb     = (const float*)d_in[10];

    float* out    = (float*)d_out;
    float* maxsc  = out;                                   // [B, Vm1]
    float* scalar = out + (size_t)BB*VM1;                  // [1]
    float* scores = out + (size_t)BB*VM1 + 1;              // [K, B, Vm1]

    const int SMEM_F_SMALL = 73728 + 2*(128*128*2);   // 139264 (NHALF=128)
    const int SMEM_F_BIG   = 73728 + 2*(256*128*2);   // 204800 (NHALF=256)

    cudaFuncSetAttribute(k_scores_mma,
                         cudaFuncAttributeMaxDynamicSharedMemorySize, S_SMEM_TOT);
    cudaFuncSetAttribute(k_mma_front<128,256,0>,
                         cudaFuncAttributeMaxDynamicSharedMemorySize, SMEM_F_SMALL);
    cudaFuncSetAttribute(k_mma_front<128,128,2>,
                         cudaFuncAttributeMaxDynamicSharedMemorySize, SMEM_F_SMALL);
    cudaFuncSetAttribute(k_mma_front<512,128,1>,
                         cudaFuncAttributeMaxDynamicSharedMemorySize, SMEM_F_BIG);

    k_prep_w<<<448, 256>>>(w1, glu1_w, att_w2);
    k_prep_emb<<<(VM1 + 7)/8, 256>>>(emb);
    k_hs<<<BB, 128>>>(hidden, mask, att_w1);

    k_mma_front<128,256,0><<<100, 256, SMEM_F_SMALL>>>(pos_emb, hidden, glu1_b, w2, att_v, mask);
    k_mma_front<128,128,2><<<100, 256, SMEM_F_SMALL>>>(pos_emb, hidden, glu1_b, w2, att_v, mask);
    k_mma_front<512,128,1><<<100, 256, SMEM_F_BIG  >>>(pos_emb, hidden, glu1_b, w2, att_v, mask);

    k_select<<<BB, 128>>>(hidden);
    k_loss<<<1, BB>>>(scalar);

    k_scores_mma<<<dim3(8, 98), 256, S_SMEM_TOT>>>(maxsc, scores);
}

// round 8
// speedup vs baseline: 2.8795x; 1.2419x over previous
#include <cuda_runtime.h>
#include <cuda_bf16.h>
#include <cstdint>

// Problem constants
#define BB   256
#define LL   50
#define DD   128
#define KK   4
#define VV   50000
#define VM1  49999
#define BL   (BB*LL)        // 12800
#define LEN_OPT 5
#define BETA_S 0.01f
#define EPS_N  1e-12f

// Arch-specific (sm_103a) feature gate: tcgen05 only exists on the 'a' target.
#if defined(__CUDA_ARCH__)
#  if defined(__CUDA_ARCH_FEAT_SM103_ALL) || defined(__CUDA_ARCH_FEAT_SM100_ALL) || \
      defined(__CUDA_ARCH_FEAT_SM101_ALL) || \
      (defined(__CUDA_ARCH_SPECIFIC__) && (__CUDA_ARCH_SPECIFIC__ >= 1000)) || \
      (defined(__CUDA_ARCH_FAMILY_SPECIFIC__) && (__CUDA_ARCH_FAMILY_SPECIFIC__ >= 1000))
#    define HAS_TCGEN05 1
#  else
#    define HAS_TCGEN05 0
#  endif
#else
#  define HAS_TCGEN05 0
#endif

// ---------------- scratch (static device globals; no allocation) ----------------
__device__ float g_hs   [BB*DD];
__device__ float g_hsw1 [BB*DD];
__device__ float g_lens [BB];
__device__ float g_beta [BL*KK];
__device__ float g_alpha[BL*KK];
__device__ __align__(16) __nv_bfloat16 g_nh_hi[BL*DD];       // tanh(cat@w1) split
__device__ __align__(16) __nv_bfloat16 g_nh_lo[BL*DD];
__device__ __align__(16) __nv_bfloat16 g_sel_hi[BB*KK*DD];   // select rows [m=b*4+k][d]
__device__ __align__(16) __nv_bfloat16 g_sel_lo[BB*KK*DD];
__device__ __align__(16) __nv_bfloat16 g_emb_hi[(size_t)VM1*DD]; // normalized emb rows
__device__ __align__(16) __nv_bfloat16 g_emb_lo[(size_t)VM1*DD];
// weights in B-operand layout [n][k], bf16 hi/lo
__device__ __align__(16) __nv_bfloat16 g_w1b_hi[128*256],  g_w1b_lo[128*256];
__device__ __align__(16) __nv_bfloat16 g_glub_hi[512*128], g_glub_lo[512*128];
__device__ __align__(16) __nv_bfloat16 g_aw2b_hi[128*128], g_aw2b_lo[128*128];

__device__ __forceinline__ float sigmoidf(float x){ return 1.0f/(1.0f+expf(-x)); }

__device__ __forceinline__ uint32_t smem_u32(const void* p) {
    uint32_t a;
    asm("{ .reg .u64 t; cvta.to.shared.u64 t, %1; cvt.u32.u64 %0, t; }" : "=r"(a) : "l"(p));
    return a;
}
#define SWZ128(x) ((x) ^ (((x) >> 3) & 0x70))

static constexpr uint64_t SMEM_DESC_BASE_SW128 =
    (uint64_t(2) << 61) | (uint64_t(1) << 46) | (uint64_t(64) << 32) | (uint64_t(1) << 16);
#define MAKE_DESC(addr) (SMEM_DESC_BASE_SW128 | ((uint64_t)((addr) >> 4) & 0x3FFF))

#if HAS_TCGEN05
__device__ __forceinline__ uint32_t elect1() {
    uint32_t p;
    asm volatile("{ .reg .pred p; elect.sync _|p, 0xFFFFFFFF; selp.b32 %0,1,0,p; }" : "=r"(p));
    return p;
}
__device__ __forceinline__ void mma_f16_ss(uint32_t d_tmem, uint64_t a_desc,
                                           uint64_t b_desc, uint32_t idesc, int en)
{
    asm volatile(
        "{\n\t.reg .pred p;\n\t"
        "setp.ne.u32 p, %4, 0;\n\t"
        "tcgen05.mma.cta_group::1.kind::f16 [%0], %1, %2, %3, {%5,%5,%5,%5}, p;\n\t}"
        :: "r"(d_tmem), "l"(a_desc), "l"(b_desc), "r"(idesc), "r"(en), "r"(0u)
        : "memory");
}
__device__ __forceinline__ void mma_f16_ts(uint32_t d_tmem, uint32_t a_tmem,
                                           uint64_t b_desc, uint32_t idesc, int en)
{
    asm volatile(
        "{\n\t.reg .pred p;\n\t"
        "setp.ne.u32 p, %4, 0;\n\t"
        "tcgen05.mma.cta_group::1.kind::f16 [%0], [%1], %2, %3, {%5,%5,%5,%5}, p;\n\t}"
        :: "r"(d_tmem), "r"(a_tmem), "l"(b_desc), "r"(idesc), "r"(en), "r"(0u)
        : "memory");
}
__device__ __forceinline__ void cp16(uint32_t dst, const void* src) {
    asm volatile("cp.async.cg.shared.global [%0], [%1], 16;" :: "r"(dst), "l"(src));
}
__device__ __forceinline__ void cp_commit() { asm volatile("cp.async.commit_group;" ::: "memory"); }
__device__ __forceinline__ void cp_wait0()  { asm volatile("cp.async.wait_group 0;" ::: "memory"); }
__device__ __forceinline__ void cp_wait1()  { asm volatile("cp.async.wait_group 1;" ::: "memory"); }
#define MBAR_WAIT(mbar, par) do {                                              \
    asm volatile(                                                              \
        "{\n\t.reg .pred P1;\n\t"                                              \
        "WL_%=:\n\t"                                                           \
        "mbarrier.try_wait.parity.acquire.cta.shared::cta.b64 P1, [%0], %1, 0x989680;\n\t" \
        "@P1 bra.uni WD_%=;\n\t"                                               \
        "bra.uni WL_%=;\n\t"                                                   \
        "WD_%=:\n\t}" :: "r"(mbar), "r"(par) : "memory");                      \
} while(0)
#define LDTM32(r, addr)                                                        \
    asm volatile(                                                              \
        "tcgen05.ld.sync.aligned.32x32b.x32.b32 "                              \
        "{%0,%1,%2,%3,%4,%5,%6,%7,%8,%9,%10,%11,%12,%13,%14,%15,"              \
        "%16,%17,%18,%19,%20,%21,%22,%23,%24,%25,%26,%27,%28,%29,%30,%31}, [%32];" \
        : "=r"(r[0]),"=r"(r[1]),"=r"(r[2]),"=r"(r[3]),"=r"(r[4]),"=r"(r[5]),"=r"(r[6]),"=r"(r[7]), \
          "=r"(r[8]),"=r"(r[9]),"=r"(r[10]),"=r"(r[11]),"=r"(r[12]),"=r"(r[13]),"=r"(r[14]),"=r"(r[15]), \
          "=r"(r[16]),"=r"(r[17]),"=r"(r[18]),"=r"(r[19]),"=r"(r[20]),"=r"(r[21]),"=r"(r[22]),"=r"(r[23]), \
          "=r"(r[24]),"=r"(r[25]),"=r"(r[26]),"=r"(r[27]),"=r"(r[28]),"=r"(r[29]),"=r"(r[30]),"=r"(r[31]) \
        : "r"(addr))
#define STTM32(addr, r)                                                        \
    asm volatile(                                                              \
        "tcgen05.st.sync.aligned.32x32b.x32.b32 [%0], "                        \
        "{%1,%2,%3,%4,%5,%6,%7,%8,%9,%10,%11,%12,%13,%14,%15,%16,"             \
        "%17,%18,%19,%20,%21,%22,%23,%24,%25,%26,%27,%28,%29,%30,%31,%32};"    \
        :: "r"(addr),                                                          \
           "r"(r[0]),"r"(r[1]),"r"(r[2]),"r"(r[3]),"r"(r[4]),"r"(r[5]),"r"(r[6]),"r"(r[7]), \
           "r"(r[8]),"r"(r[9]),"r"(r[10]),"r"(r[11]),"r"(r[12]),"r"(r[13]),"r"(r[14]),"r"(r[15]), \
           "r"(r[16]),"r"(r[17]),"r"(r[18]),"r"(r[19]),"r"(r[20]),"r"(r[21]),"r"(r[22]),"r"(r[23]), \
           "r"(r[24]),"r"(r[25]),"r"(r[26]),"r"(r[27]),"r"(r[28]),"r"(r[29]),"r"(r[30]),"r"(r[31]) \
        : "memory")
#endif

__device__ __forceinline__ ushort bf_hi_us(float v, float& rem) {
    __nv_bfloat16 hb = __float2bfloat16(v);
    rem = v - __bfloat162float(hb);
    return *reinterpret_cast<ushort*>(&hb);
}
__device__ __forceinline__ ushort bf_us(float v) {
    __nv_bfloat16 b = __float2bfloat16(v);
    return *reinterpret_cast<ushort*>(&b);
}

// ---------------- kernel 1: masked mean hs, lens, hs@att_w1 ----------------
__global__ void k_hs(const float* __restrict__ hidden, const int* __restrict__ mask,
                     const float* __restrict__ att_w1)
{
    int b = blockIdx.x, t = threadIdx.x;
    __shared__ float hs_sm[DD];
    float acc = 0.f, sm = 0.f;
    for (int l = 0; l < LL; l++) {
        float mk = (float)mask[b*LL + l];
        sm  += mk;
        acc += hidden[(b*LL + l)*DD + t] * mk;
    }
    float hsv = acc / sm;
    hs_sm[t] = hsv;
    g_hs[b*DD + t] = hsv;
    if (t == 0) g_lens[b] = sm - (float)LEN_OPT;
    __syncthreads();
    float a2 = 0.f;
    #pragma unroll 8
    for (int e = 0; e < DD; e++) a2 += hs_sm[e] * att_w1[e*DD + t];
    g_hsw1[b*DD + t] = a2;
}

// ---------------- merged prep: emb normalize/split (blocks 0..6249) + weights ------
#define NPE_BLOCKS 6250
__global__ void k_prep(const float* __restrict__ emb, const float* __restrict__ w1,
                       const float* __restrict__ glu1_w, const float* __restrict__ att_w2)
{
    if (blockIdx.x < NPE_BLOCKS) {
        int w = threadIdx.x >> 5, lane = threadIdx.x & 31;
        int v = blockIdx.x*8 + w;
        if (v >= VM1) return;
        float4 x = *(const float4*)(emb + (size_t)(1 + v)*DD + lane*4);
        float s = x.x*x.x + x.y*x.y + x.z*x.z + x.w*x.w;
        #pragma unroll
        for (int o = 16; o > 0; o >>= 1) s += __shfl_xor_sync(0xffffffffu, s, o);
        float inv = 1.0f / fmaxf(sqrtf(s), EPS_N);
        float n[4] = {x.x*inv, x.y*inv, x.z*inv, x.w*inv};
        __nv_bfloat16 hi[4], lo[4];
        #pragma unroll
        for (int i = 0; i < 4; i++) {
            hi[i] = __float2bfloat16(n[i]);
            lo[i] = __float2bfloat16(n[i] - __bfloat162float(hi[i]));
        }
        *(uint64_t*)(&g_emb_hi[(size_t)v*DD + lane*4]) = *(uint64_t*)hi;
        *(uint64_t*)(&g_emb_lo[(size_t)v*DD + lane*4]) = *(uint64_t*)lo;
    } else {
        int i = (blockIdx.x - NPE_BLOCKS)*256 + threadIdx.x;
        float v; __nv_bfloat16 hi, lo;
        if (i < 32768) {                 // w1 [256k,128n] -> [128n][256k]
            int n = i >> 8, k = i & 255;
            v = w1[k*128 + n];
            hi = __float2bfloat16(v); lo = __float2bfloat16(v - __bfloat162float(hi));
            g_w1b_hi[i] = hi; g_w1b_lo[i] = lo;
        } else if (i < 32768 + 65536) {  // glu1_w [128k,512n] -> [512n][128k]
            int j = i - 32768;
            int n = j >> 7, k = j & 127;
            v = glu1_w[k*512 + n];
            hi = __float2bfloat16(v); lo = __float2bfloat16(v - __bfloat162float(hi));
            g_glub_hi[j] = hi; g_glub_lo[j] = lo;
        } else if (i < 114688) {         // att_w2 [128k,128n] -> [128n][128k]
            int j = i - 98304;
            int n = j >> 7, k = j & 127;
            v = att_w2[k*128 + n];
            hi = __float2bfloat16(v); lo = __float2bfloat16(v - __bfloat162float(hi));
            g_aw2b_hi[j] = hi; g_aw2b_lo[j] = lo;
        }
    }
}

// ---------------- front-end smem layout --------------------------------------------
#define F_OFF_TMEM 0
#define F_OFF_MBAR 8
#define F_OFF_AUX  64
#define F_OFF_AH   8192
#define F_OFF_AL   (8192 + 32768)
#define F_OFF_BH   73728
#define FRONT_IDESC(NHALF) ((1u<<4) | (1u<<7) | (1u<<10) | ((NHALF/8)<<17) | (8u<<24))

// ---------------- fused front modes 0 & 2 in ONE launch (grid=200) -----------------
// blocks [0,100): mode0  nh = tanh(cat(pos,hidden)@w1)  -> g_nh hi/lo
// blocks [100,200): mode2 alpha = sigmoid(tanh(hsw1 + hidden@att_w2)@att_v)
__global__ void __launch_bounds__(256, 1) k_front02(
    const float* __restrict__ pos_emb, const float* __restrict__ hidden,
    const float* __restrict__ att_v)
{
#if HAS_TCGEN05
    extern __shared__ char smem[];
    uint32_t sbase = smem_u32(smem);
    int tid = threadIdx.x, wid = tid >> 5, lane = tid & 31;
    int mode  = (blockIdx.x < 100) ? 0 : 2;
    int mtile = (mode == 0) ? blockIdx.x : blockIdx.x - 100;

    float* aux = (float*)(smem + F_OFF_AUX);
    if (mode == 2) for (int i = tid; i < 512; i += 256) aux[i] = att_v[i];

    if (tid == 0)
        asm volatile("mbarrier.init.shared.b64 [%0], 1;" :: "r"(sbase + F_OFF_MBAR) : "memory");
    if (wid == 4)
        asm volatile("tcgen05.alloc.cta_group::1.sync.aligned.shared::cta.b32 [%0], %1;"
                     :: "r"(sbase + F_OFF_TMEM), "r"(128u) : "memory");
    __syncthreads();
    uint32_t tmem;
    asm volatile("ld.shared.b32 %0, [%1];" : "=r"(tmem) : "r"(sbase + F_OFF_TMEM));

    int KCHr = (mode == 0) ? 2 : 1;
    int KD   = (mode == 0) ? 256 : 128;
    const __nv_bfloat16* bhsrc = (mode == 0) ? g_w1b_hi : g_aw2b_hi;
    const __nv_bfloat16* blsrc = (mode == 0) ? g_w1b_lo : g_aw2b_lo;

    for (int kc = 0; kc < KCHr; kc++) {
        // stage A [128m x 128k] hi/lo (fp32 -> split)
        for (int i = tid; i < 128*16; i += 256) {
            int r = i >> 4, c8 = i & 15;
            int m = mtile*128 + r;
            int col = (c8 >> 3)*64 + (c8 & 7)*8;
            const float* src;
            if (mode == 0) src = (kc == 0) ? (pos_emb + (m % LL)*DD + col)
                                           : (hidden + (size_t)m*DD + col);
            else           src = hidden + (size_t)m*DD + col;
            float f[8];
            *(float4*)f       = *(const float4*)src;
            *(float4*)(f + 4) = *(const float4*)(src + 4);
            __align__(16) ushort h[8], l[8];
            #pragma unroll
            for (int q = 0; q < 8; q++) { float rem; h[q] = bf_hi_us(f[q], rem); l[q] = bf_us(rem); }
            uint32_t byte = (uint32_t)((c8 >> 3)*16 + (r >> 3))*1024u
                          + (uint32_t)(r & 7)*128u + (uint32_t)(c8 & 7)*16u;
            uint32_t sw = SWZ128(byte);
            *(uint4*)(smem + F_OFF_AH + sw) = *(uint4*)h;
            *(uint4*)(smem + F_OFF_AL + sw) = *(uint4*)l;
        }
        // stage B [128n x 128k] hi/lo
        for (int i = tid; i < 128*16; i += 256) {
            int r = i >> 4, c8 = i & 15;
            int col = kc*128 + (c8 >> 3)*64 + (c8 & 7)*8;
            int off = r*KD + col;
            uint32_t byte = (uint32_t)((c8 >> 3)*16 + (r >> 3))*1024u
                          + (uint32_t)(r & 7)*128u + (uint32_t)(c8 & 7)*16u;
            uint32_t sw = SWZ128(byte);
            *(uint4*)(smem + F_OFF_BH + sw)         = *(const uint4*)(bhsrc + off);
            *(uint4*)(smem + F_OFF_BH + 32768 + sw) = *(const uint4*)(blsrc + off);
        }
        __syncthreads();
        if (wid == 4 && elect1()) {
            asm volatile("fence.proxy.async.shared::cta;" ::: "memory");
            uint64_t dAh = MAKE_DESC(sbase + F_OFF_AH);
            uint64_t dAl = MAKE_DESC(sbase + F_OFF_AL);
            uint64_t dBh = MAKE_DESC(sbase + F_OFF_BH);
            uint64_t dBl = MAKE_DESC(sbase + F_OFF_BH + 32768);
            uint64_t ad[3] = { dAh, dAh, dAl };
            uint64_t bd[3] = { dBh, dBl, dBh };
            #pragma unroll
            for (int p = 0; p < 3; p++) {
                #pragma unroll
                for (int s = 0; s < 8; s++) {
                    uint64_t a = ad[p] + (uint64_t)((s >> 2)*1024 + (s & 3)*2);
                    uint64_t b = bd[p] + (uint64_t)((s >> 2)*1024 + (s & 3)*2);
                    mma_f16_ss(tmem, a, b, FRONT_IDESC(128),
                               !(kc == 0 && p == 0 && s == 0));
                }
            }
            asm volatile(
                "tcgen05.commit.cta_group::1.mbarrier::arrive::one.shared::cluster.b64 [%0];"
                :: "r"(sbase + F_OFF_MBAR) : "memory");
        }
        MBAR_WAIT(sbase + F_OFF_MBAR, (uint32_t)(kc & 1));
    }
    asm volatile("tcgen05.fence::after_thread_sync;" ::: "memory");

    if (wid < 4) {
        int m = mtile*128 + wid*32 + lane;
        if (mode == 0) {
            uint32_t* dsth = (uint32_t*)g_nh_hi + m*64;
            uint32_t* dstl = (uint32_t*)g_nh_lo + m*64;
            #pragma unroll 1
            for (int ch = 0; ch < 4; ch++) {
                uint32_t r[32];
                LDTM32(r, tmem + ch*32);
                asm volatile("tcgen05.wait::ld.sync.aligned;" ::: "memory");
                uint32_t hu[16], lu[16];
                #pragma unroll
                for (int j = 0; j < 16; j++) {
                    float v0 = tanhf(__uint_as_float(r[2*j]));
                    float v1 = tanhf(__uint_as_float(r[2*j + 1]));
                    float r0, r1;
                    ushort h0 = bf_hi_us(v0, r0), h1 = bf_hi_us(v1, r1);
                    hu[j] = ((uint32_t)h1 << 16) | h0;
                    lu[j] = ((uint32_t)bf_us(r1) << 16) | bf_us(r0);
                }
                #pragma unroll
                for (int q = 0; q < 4; q++) {
                    *(uint4*)(dsth + ch*16 + q*4) = make_uint4(hu[4*q], hu[4*q+1], hu[4*q+2], hu[4*q+3]);
                    *(uint4*)(dstl + ch*16 + q*4) = make_uint4(lu[4*q], lu[4*q+1], lu[4*q+2], lu[4*q+3]);
                }
            }
        } else {
            float acc[4] = {};
            const float* hsrow = g_hsw1 + (m / LL)*DD;
            #pragma unroll 1
            for (int ch = 0; ch < 4; ch++) {
                uint32_t r[32];
                LDTM32(r, tmem + ch*32);
                asm volatile("tcgen05.wait::ld.sync.aligned;" ::: "memory");
                #pragma unroll
                for (int j = 0; j < 32; j++) {
                    int c = ch*32 + j;
                    float t = tanhf(__uint_as_float(r[j]) + hsrow[c]);
                    #pragma unroll
                    for (int k = 0; k < 4; k++) acc[k] += t * aux[c*4 + k];
                }
            }
            float4 al;
            al.x = sigmoidf(acc[0]); al.y = sigmoidf(acc[1]);
            al.z = sigmoidf(acc[2]); al.w = sigmoidf(acc[3]);
            *(float4*)(g_alpha + m*4) = al;
        }
    }
    __syncthreads();
    if (wid == 4)
        asm volatile("tcgen05.dealloc.cta_group::1.sync.aligned.b32 %0, %1;"
                     :: "r"(tmem), "r"(128u));
#else
    int tid = threadIdx.x;
    if (tid >= 128) return;
    int mode  = (blockIdx.x < 100) ? 0 : 2;
    int mtile = (mode == 0) ? blockIdx.x : blockIdx.x - 100;
    int m = mtile*128 + tid;
    if (mode == 0) {
        for (int n = 0; n < 128; n++) {
            float acc = 0.f;
            for (int k = 0; k < 256; k++) {
                float a = (k < 128) ? pos_emb[(m % LL)*DD + k] : hidden[(size_t)m*DD + k - 128];
                float b = __bfloat162float(g_w1b_hi[n*256 + k]) + __bfloat162float(g_w1b_lo[n*256 + k]);
                acc += a * b;
            }
            float v = tanhf(acc);
            __nv_bfloat16 hb = __float2bfloat16(v);
            g_nh_hi[m*DD + n] = hb;
            g_nh_lo[m*DD + n] = __float2bfloat16(v - __bfloat162float(hb));
        }
    } else {
        float acc[4] = {};
        for (int n = 0; n < 128; n++) {
            float x = 0.f;
            for (int k = 0; k < 128; k++)
                x += hidden[(size_t)m*DD + k] *
                     (__bfloat162float(g_aw2b_hi[n*128 + k]) + __bfloat162float(g_aw2b_lo[n*128 + k]));
            float t = tanhf(x + g_hsw1[(m / LL)*DD + n]);
            for (int k = 0; k < 4; k++) acc[k] += t * att_v[n*4 + k];
        }
        for (int k = 0; k < 4; k++) g_alpha[m*4 + k] = sigmoidf(acc[k]);
    }
#endif
}

// ---------------- front mode1 (GLU+beta), unchanged from R7 ------------------------
template<int NTOT, int KDIM, int MODE>
__global__ void __launch_bounds__(256, 1) k_mma_front(
    const float* __restrict__ pos_emb, const float* __restrict__ hidden,
    const float* __restrict__ glu1_b, const float* __restrict__ w2,
    const float* __restrict__ att_v, const int* __restrict__ mask)
{
    constexpr int NHALF = (NTOT > 256) ? 256 : NTOT;
    constexpr int NH  = NTOT / NHALF;
    constexpr int KCH = KDIM / 128;
#if HAS_TCGEN05
    constexpr int BBYTES = NHALF * 128 * 2;
    extern __shared__ char smem[];
    uint32_t sbase = smem_u32(smem);
    int tid = threadIdx.x, wid = tid >> 5, lane = tid & 31;
    int mtile = blockIdx.x;

    float* aux = (float*)(smem + F_OFF_AUX);
    if (MODE == 1) for (int i = tid; i < 512; i += 256) { aux[i] = glu1_b[i]; aux[512 + i] = w2[i]; }

    if (tid == 0)
        asm volatile("mbarrier.init.shared.b64 [%0], 1;" :: "r"(sbase + F_OFF_MBAR) : "memory");
    if (wid == 4)
        asm volatile("tcgen05.alloc.cta_group::1.sync.aligned.shared::cta.b32 [%0], %1;"
                     :: "r"(sbase + F_OFF_TMEM), "r"((uint32_t)NTOT) : "memory");
    __syncthreads();
    uint32_t tmem;
    asm volatile("ld.shared.b32 %0, [%1];" : "=r"(tmem) : "r"(sbase + F_OFF_TMEM));

    int iter = 0;
    for (int kc = 0; kc < KCH; kc++) {
        for (int i = tid; i < 128*16; i += 256) {
            int r = i >> 4, c8 = i & 15;
            uint32_t byte = (uint32_t)((c8 >> 3)*16 + (r >> 3))*1024u
                          + (uint32_t)(r & 7)*128u + (uint32_t)(c8 & 7)*16u;
            uint32_t sw = SWZ128(byte);
            int off = (mtile*128 + r)*DD + (c8 >> 3)*64 + (c8 & 7)*8;
            *(uint4*)(smem + F_OFF_AH + sw) = *(const uint4*)(g_nh_hi + off);
            *(uint4*)(smem + F_OFF_AL + sw) = *(const uint4*)(g_nh_lo + off);
        }
        for (int h = 0; h < NH; h++) {
            for (int i = tid; i < NHALF*16; i += 256) {
                int r = i >> 4, c8 = i & 15;
                int n = h*NHALF + r;
                int col = kc*128 + (c8 >> 3)*64 + (c8 & 7)*8;
                int off = n*KDIM + col;
                uint32_t byte = (uint32_t)((c8 >> 3)*(NHALF/8) + (r >> 3))*1024u
                              + (uint32_t)(r & 7)*128u + (uint32_t)(c8 & 7)*16u;
                uint32_t sw = SWZ128(byte);
                *(uint4*)(smem + F_OFF_BH + sw)          = *(const uint4*)(g_glub_hi + off);
                *(uint4*)(smem + F_OFF_BH + BBYTES + sw) = *(const uint4*)(g_glub_lo + off);
            }
            __syncthreads();
            if (wid == 4 && elect1()) {
                asm volatile("fence.proxy.async.shared::cta;" ::: "memory");
                uint64_t dAh = MAKE_DESC(sbase + F_OFF_AH);
                uint64_t dAl = MAKE_DESC(sbase + F_OFF_AL);
                uint64_t dBh = MAKE_DESC(sbase + F_OFF_BH);
                uint64_t dBl = MAKE_DESC(sbase + F_OFF_BH + BBYTES);
                uint64_t ad[3] = { dAh, dAh, dAl };
                uint64_t bd[3] = { dBh, dBl, dBh };
                #pragma unroll
                for (int p = 0; p < 3; p++) {
                    #pragma unroll
                    for (int s = 0; s < 8; s++) {
                        uint64_t a = ad[p] + (uint64_t)((s >> 2)*1024 + (s & 3)*2);
                        uint64_t b = bd[p] + (uint64_t)((s >> 2)*(NHALF*8) + (s & 3)*2);
                        mma_f16_ss(tmem + h*NHALF, a, b, FRONT_IDESC(NHALF),
                                   !(kc == 0 && p == 0 && s == 0));
                    }
                }
                asm volatile(
                    "tcgen05.commit.cta_group::1.mbarrier::arrive::one.shared::cluster.b64 [%0];"
                    :: "r"(sbase + F_OFF_MBAR) : "memory");
            }
            MBAR_WAIT(sbase + F_OFF_MBAR, (uint32_t)(iter & 1));
            iter++;
        }
    }
    asm volatile("tcgen05.fence::after_thread_sync;" ::: "memory");

    if (wid < 4) {
        int m = mtile*128 + wid*32 + lane;
        float acc[4] = {};
        #pragma unroll 1
        for (int ch = 0; ch < 16; ch++) {
            uint32_t r[32];
            LDTM32(r, tmem + ch*32);
            asm volatile("tcgen05.wait::ld.sync.aligned;" ::: "memory");
            int k = ch >> 2;
            float a = 0.f;
            #pragma unroll
            for (int j = 0; j < 32; j++) {
                int c = ch*32 + j;
                int d = c & 127;
                float s = sigmoidf(__uint_as_float(r[j]) + aux[c]);
                a += s * aux[512 + d*4 + k];
            }
            acc[k] += a;
        }
        float mk = (float)mask[m];
        float4 be;
        be.x = acc[0] * (0.5f + g_alpha[m*4+0]) * mk;
        be.y = acc[1] * (0.5f + g_alpha[m*4+1]) * mk;
        be.z = acc[2] * (0.5f + g_alpha[m*4+2]) * mk;
        be.w = acc[3] * (0.5f + g_alpha[m*4+3]) * mk;
        *(float4*)(g_beta + m*4) = be;
    }
    __syncthreads();
    if (wid == 4)
        asm volatile("tcgen05.dealloc.cta_group::1.sync.aligned.b32 %0, %1;"
                     :: "r"(tmem), "r"((uint32_t)NTOT));
#else
    int tid = threadIdx.x;
    if (tid >= 128) return;
    int m = blockIdx.x*128 + tid;
    float acc[4] = {};
    for (int n = 0; n < 512; n++) {
        float x = 0.f;
        for (int k = 0; k < 128; k++) {
            float a = __bfloat162float(g_nh_hi[m*DD + k]) + __bfloat162float(g_nh_lo[m*DD + k]);
            x += a * (__bfloat162float(g_glub_hi[n*128 + k]) + __bfloat162float(g_glub_lo[n*128 + k]));
        }
        float s = sigmoidf(x + glu1_b[n]);
        acc[n >> 7] += s * w2[(n & 127)*4 + (n >> 7)];
    }
    float mk = (float)mask[m];
    for (int k = 0; k < 4; k++)
        g_beta[m*4 + k] = acc[k] * (0.5f + g_alpha[m*4 + k]) * mk;
#endif
}

// ---------------- select (blocks 0..255) + loss (block 256) ------------------------
__global__ void k_sel_loss(const float* __restrict__ hidden, float* __restrict__ out_scalar)
{
    if (blockIdx.x < BB) {
        if (threadIdx.x >= 128) return;
        int b = blockIdx.x, t = threadIdx.x;
        float acc[4] = {};
        for (int l = 0; l < LL; l++) {
            float h = hidden[(b*LL + l)*DD + t];
            float4 be = *(const float4*)(&g_beta[(b*LL + l)*4]);
            acc[0] += be.x*h; acc[1] += be.y*h; acc[2] += be.z*h; acc[3] += be.w*h;
        }
        #pragma unroll
        for (int k = 0; k < 4; k++) {
            float v = acc[k];
            __nv_bfloat16 hi = __float2bfloat16(v);
            __nv_bfloat16 lo = __float2bfloat16(v - __bfloat162float(hi));
            g_sel_hi[(b*4 + k)*DD + t] = hi;
            g_sel_lo[(b*4 + k)*DD + t] = lo;
        }
    } else {
        int b = threadIdx.x;
        float n2[4] = {};
        for (int l = 0; l < LL; l++) {
            float4 be = *(const float4*)(&g_beta[(b*LL + l)*4]);
            n2[0]+=be.x*be.x; n2[1]+=be.y*be.y; n2[2]+=be.z*be.z; n2[3]+=be.w*be.w;
        }
        float inv[4];
        #pragma unroll
        for (int k = 0; k < 4; k++) inv[k] = 1.0f / fmaxf(sqrtf(n2[k]), EPS_N);
        float G[6] = {};
        for (int l = 0; l < LL; l++) {
            float4 be = *(const float4*)(&g_beta[(b*LL + l)*4]);
            float v0=be.x*inv[0], v1=be.y*inv[1], v2=be.z*inv[2], v3=be.w*inv[3];
            G[0]+=v0*v1; G[1]+=v0*v2; G[2]+=v0*v3;
            G[3]+=v1*v2; G[4]+=v1*v3; G[5]+=v2*v3;
        }
        float sim = 0.f;
        #pragma unroll
        for (int i = 0; i < 6; i++) sim += fabsf(G[i]);
        sim *= (2.0f / (KK*(KK-1)));
        float lossb = sigmoidf(sim * g_lens[b]);
        __shared__ float red[BB];
        red[b] = lossb;  __syncthreads();
        for (int s = BB/2; s > 0; s >>= 1) {
            if (b < s) red[b] += red[b + s];
            __syncthreads();
        }
        if (b == 0) *out_scalar = red[0] * BETA_S;
    }
}

// ---------------- scores: persistent CTAs, TS-mode MMA, 8-warp epilogue ------------
// grid (8 mtiles, 18): CTA (x,y) handles vtiles y, y+18, ... (<391). A in TMEM.
// TMEM: D0 @0 (128), D1 @128 (128), A_hi @256 (64), A_lo @320 (64).
#define SC_TILES 391
#define SC_STRIDE 18
#define S_IDESC ((1u<<4) | (1u<<7) | (1u<<10) | ((128/8)<<17) | (8u<<24))
#define S2_TMEM  0
#define S2_MBAR0 8
#define S2_MBAR1 16
#define S2_B0    1024
#define S2_B1    (1024 + 65536)
#define S2_STG   (1024 + 131072)              // 132096; 8 warps x 32x33 floats
#define S2_SMEM_TOT (132096 + 8*32*33*4)      // 165888

#if HAS_TCGEN05
__device__ __forceinline__ void s2_load_b(uint32_t bufbase, int vtile, int tid)
{
    int vbase = vtile * 128;
    #pragma unroll 4
    for (int i = tid; i < 4096; i += 256) {
        int half = i >> 11, rem = i & 2047;
        int r = rem >> 4, c8 = rem & 15;
        int v = vbase + r; if (v > VM1 - 1) v = VM1 - 1;
        const __nv_bfloat16* src = (half ? g_emb_lo : g_emb_hi)
                                 + (size_t)v*DD + (c8 >> 3)*64 + (c8 & 7)*8;
        uint32_t byte = (uint32_t)((c8 >> 3)*16 + (r >> 3))*1024u
                      + (uint32_t)(r & 7)*128u + (uint32_t)(c8 & 7)*16u;
        cp16(bufbase + half*32768u + SWZ128(byte), src);
    }
    cp_commit();
}
__device__ __forceinline__ void s2_mma(uint32_t tmem, int dhalf, uint32_t sbase,
                                       uint32_t bufoff, uint32_t mbar)
{
    asm volatile("fence.proxy.async.shared::cta;" ::: "memory");
    uint64_t dBh = MAKE_DESC(sbase + bufoff);
    uint64_t dBl = MAKE_DESC(sbase + bufoff + 32768);
    uint32_t d  = tmem + (dhalf << 7);
    uint32_t aH = tmem + 256, aL = tmem + 320;
    uint32_t ap[3] = { aH, aH, aL };
    uint64_t bp[3] = { dBh, dBl, dBh };
    #pragma unroll
    for (int p = 0; p < 3; p++) {
        #pragma unroll
        for (int s = 0; s < 8; s++) {
            mma_f16_ts(d, ap[p] + s*8,
                       bp[p] + (uint64_t)((s >> 2)*1024 + (s & 3)*2),
                       S_IDESC, !(p == 0 && s == 0));
        }
    }
    asm volatile(
        "tcgen05.commit.cta_group::1.mbarrier::arrive::one.shared::cluster.b64 [%0];"
        :: "r"(mbar) : "memory");
}
#endif

__global__ void __launch_bounds__(256, 1) k_scores_mma(
        float* __restrict__ maxsc, float* __restrict__ scores)
{
#if HAS_TCGEN05
    extern __shared__ char smem[];
    uint32_t sbase = smem_u32(smem);
    int tid = threadIdx.x, wid = tid >> 5, lane = tid & 31;
    int mtile = blockIdx.x;
    int y = blockIdx.y;
    int nt = (SC_TILES - y + SC_STRIDE - 1) / SC_STRIDE;   // >= 21

    if (tid == 0) {
        asm volatile("mbarrier.init.shared.b64 [%0], 1;" :: "r"(sbase + S2_MBAR0) : "memory");
        asm volatile("mbarrier.init.shared.b64 [%0], 1;" :: "r"(sbase + S2_MBAR1) : "memory");
    }
    if (wid == 0)
        asm volatile("tcgen05.alloc.cta_group::1.sync.aligned.shared::cta.b32 [%0], %1;"
                     :: "r"(sbase + S2_TMEM), "r"(512u) : "memory");
    __syncthreads();
    uint32_t tmem;
    asm volatile("ld.shared.b32 %0, [%1];" : "=r"(tmem) : "r"(sbase + S2_TMEM));

    // prologue: B(0), B(1) via cp.async; A -> TMEM
    s2_load_b(sbase + S2_B0, y, tid);
    s2_load_b(sbase + S2_B1, y + SC_STRIDE, tid);
    if (tid < 128) {
        int m = mtile*128 + tid;
        const uint32_t* ph = (const uint32_t*)g_sel_hi + (size_t)m*64;
        const uint32_t* pl = (const uint32_t*)g_sel_lo + (size_t)m*64;
        uint32_t woff = (uint32_t)(tid >> 5) << 21;
        uint32_t a[32];
        #pragma unroll
        for (int q = 0; q < 32; q++) a[q] = ph[q];
        STTM32(tmem + 256 + woff, a);
        #pragma unroll
        for (int q = 0; q < 32; q++) a[q] = ph[32 + q];
        STTM32(tmem + 288 + woff, a);
        #pragma unroll
        for (int q = 0; q < 32; q++) a[q] = pl[q];
        STTM32(tmem + 320 + woff, a);
        #pragma unroll
        for (int q = 0; q < 32; q++) a[q] = pl[32 + q];
        STTM32(tmem + 352 + woff, a);
        asm volatile("tcgen05.wait::st.sync.aligned;" ::: "memory");
    }
    cp_wait1();                        // B(0) resident (B(1) still in flight)
    __syncthreads();
    if (wid == 0 && elect1())
        s2_mma(tmem, 0, sbase, S2_B0, sbase + S2_MBAR0);

    int sub = wid & 3, h = wid >> 2;
    float* stg = (float*)(smem + S2_STG + wid*(32*33*4));

    for (int i = 0; i < nt; i++) {
        cp_wait0();                                        // B(i+1) resident
        MBAR_WAIT(sbase + ((i & 1) ? S2_MBAR1 : S2_MBAR0), (uint32_t)((i >> 1) & 1));
        asm volatile("tcgen05.fence::after_thread_sync;" ::: "memory");
        __syncthreads();

        if (i + 1 < nt && wid == 0 && elect1())
            s2_mma(tmem, (i + 1) & 1, sbase,
                   ((i + 1) & 1) ? S2_B1 : S2_B0,
                   sbase + (((i + 1) & 1) ? S2_MBAR1 : S2_MBAR0));
        if (i + 2 < nt)
            s2_load_b(sbase + ((i & 1) ? S2_B1 : S2_B0), y + (i + 2)*SC_STRIDE, tid);

        // 8-warp epilogue of tile i from TMEM half i&1
        uint32_t dbase = tmem + ((i & 1) << 7);
        int vb = (y + i*SC_STRIDE)*128;
        #pragma unroll 1
        for (int cc = 0; cc < 2; cc++) {
            int col0 = h*64 + cc*32;
            uint32_t r[32];
            LDTM32(r, dbase + col0);
            asm volatile("tcgen05.wait::ld.sync.aligned;" ::: "memory");
            #pragma unroll
            for (int c = 0; c < 32; c++) stg[lane*33 + c] = __uint_as_float(r[c]);
            __syncwarp();
            int v = vb + col0 + lane;
            bool ok = v < VM1;
            #pragma unroll
            for (int lb = 0; lb < 8; lb++) {
                int b = mtile*32 + sub*8 + lb;
                float mx = -3.402823466e38f;
                #pragma unroll
                for (int j = 0; j < 4; j++) {
                    float x = stg[(lb*4 + j)*33 + lane];
                    if (ok) __stcs(&scores[((size_t)j*BB + b)*VM1 + v], x);
                    mx = fmaxf(mx, x);
                }
                if (ok) __stcs(&maxsc[(size_t)b*VM1 + v], mx);
            }
            __syncwarp();
        }
    }
    __syncthreads();
    if (wid == 0)
        asm volatile("tcgen05.dealloc.cta_group::1.sync.aligned.b32 %0, %1;"
                     :: "r"(tmem), "r"(512u));
#else
    int tid = threadIdx.x;
    int mtile = blockIdx.x;
    int y = blockIdx.y;
    for (int vt = y; vt < SC_TILES; vt += SC_STRIDE) {
        int vbase = vt*128;
        for (int p = tid; p < 32*128; p += 256) {
            int bl = p >> 7, vv = vbase + (p & 127);
            if (vv >= VM1) continue;
            int b = mtile*32 + bl;
            float mx = -3.402823466e38f;
            for (int k = 0; k < 4; k++) {
                int m = (b*4 + k);
                float acc = 0.f;
                for (int d = 0; d < DD; d++) {
                    float a = __bfloat162float(g_sel_hi[m*DD + d]) + __bfloat162float(g_sel_lo[m*DD + d]);
                    float e = __bfloat162float(g_emb_hi[(size_t)vv*DD + d]) + __bfloat162float(g_emb_lo[(size_t)vv*DD + d]);
                    acc += a * e;
                }
                scores[((size_t)k*BB + b)*VM1 + vv] = acc;
                mx = fmaxf(mx, acc);
            }
            maxsc[(size_t)b*VM1 + vv] = mx;
        }
    }
#endif
}

// ---------------- launch ------------------------------------------------------------
extern "C" void kernel_launch(void* const* d_in, const int* in_sizes, int n_in,
                              void* d_out, int out_size)
{
    const float* hidden  = (const float*)d_in[0];
    const int*   mask    = (const int*)  d_in[1];
    const float* pos_emb = (const float*)d_in[2];
    const float* w1      = (const float*)d_in[3];
    const float* w2      = (const float*)d_in[4];
    const float* glu1_w  = (const float*)d_in[5];
    const float* glu1_b  = (const float*)d_in[6];
    const float* att_w1  = (const float*)d_in[7];
    const float* att_w2  = (const float*)d_in[8];
    const float* att_v   = (const float*)d_in[9];
    const float* emb     = (const float*)d_in[10];

    float* out    = (float*)d_out;
    float* maxsc  = out;                                   // [B, Vm1]
    float* scalar = out + (size_t)BB*VM1;                  // [1]
    float* scores = out + (size_t)BB*VM1 + 1;              // [K, B, Vm1]

    const int SMEM_F_SMALL = 73728 + 2*(128*128*2);   // 139264 (NHALF=128)
    const int SMEM_F_BIG   = 73728 + 2*(256*128*2);   // 204800 (NHALF=256)

    cudaFuncSetAttribute(k_scores_mma,
                         cudaFuncAttributeMaxDynamicSharedMemorySize, S2_SMEM_TOT);
    cudaFuncSetAttribute(k_front02,
                         cudaFuncAttributeMaxDynamicSharedMemorySize, SMEM_F_SMALL);
    cudaFuncSetAttribute(k_mma_front<512,128,1>,
                         cudaFuncAttributeMaxDynamicSharedMemorySize, SMEM_F_BIG);

    k_prep<<<NPE_BLOCKS + 448, 256>>>(emb, w1, glu1_w, att_w2);
    k_hs<<<BB, 128>>>(hidden, mask, att_w1);

    k_front02<<<200, 256, SMEM_F_SMALL>>>(pos_emb, hidden, att_v);
    k_mma_front<512,128,1><<<100, 256, SMEM_F_BIG>>>(pos_emb, hidden, glu1_b, w2, att_v, mask);

    k_sel_loss<<<BB + 1, 256>>>(hidden, scalar);

    k_scores_mma<<<dim3(8, SC_STRIDE), 256, S2_SMEM_TOT>>>(maxsc, scores);
}

// round 9
// speedup vs baseline: 3.3933x; 1.1784x over previous
#include <cuda_runtime.h>
#include <cuda_bf16.h>
#include <cstdint>

// Problem constants
#define BB   256
#define LL   50
#define DD   128
#define KK   4
#define VV   50000
#define VM1  49999
#define BL   (BB*LL)        // 12800
#define LEN_OPT 5
#define BETA_S 0.01f
#define EPS_N  1e-12f

// Arch-specific (sm_103a) feature gate
#if defined(__CUDA_ARCH__)
#  if defined(__CUDA_ARCH_FEAT_SM103_ALL) || defined(__CUDA_ARCH_FEAT_SM100_ALL) || \
      defined(__CUDA_ARCH_FEAT_SM101_ALL) || \
      (defined(__CUDA_ARCH_SPECIFIC__) && (__CUDA_ARCH_SPECIFIC__ >= 1000)) || \
      (defined(__CUDA_ARCH_FAMILY_SPECIFIC__) && (__CUDA_ARCH_FAMILY_SPECIFIC__ >= 1000))
#    define HAS_TCGEN05 1
#  else
#    define HAS_TCGEN05 0
#  endif
#else
#  define HAS_TCGEN05 0
#endif

// ---------------- scratch (static device globals; no allocation) ----------------
__device__ float g_hsw1 [BB*DD];
__device__ float g_lens [BB];
__device__ float g_posw1[50*DD];                               // pos_emb @ w1_top (fp32)
__device__ float g_beta [BL*KK];
__device__ __align__(16) __nv_bfloat16 g_sel_hi[BB*KK*DD];
__device__ __align__(16) __nv_bfloat16 g_sel_lo[BB*KK*DD];
__device__ __align__(16) __nv_bfloat16 g_emb_hi[(size_t)VM1*DD];
__device__ __align__(16) __nv_bfloat16 g_emb_lo[(size_t)VM1*DD];
// weights in B-operand layout [n][k], bf16 hi/lo
__device__ __align__(16) __nv_bfloat16 g_w1b_hi[128*256],  g_w1b_lo[128*256];
__device__ __align__(16) __nv_bfloat16 g_glub_hi[512*128], g_glub_lo[512*128];
__device__ __align__(16) __nv_bfloat16 g_aw2b_hi[128*128], g_aw2b_lo[128*128];

__device__ __forceinline__ float sigmoidf(float x){ return 1.0f/(1.0f+expf(-x)); }

__device__ __forceinline__ uint32_t smem_u32(const void* p) {
    uint32_t a;
    asm("{ .reg .u64 t; cvta.to.shared.u64 t, %1; cvt.u32.u64 %0, t; }" : "=r"(a) : "l"(p));
    return a;
}
#define SWZ128(x) ((x) ^ (((x) >> 3) & 0x70))

static constexpr uint64_t SMEM_DESC_BASE_SW128 =
    (uint64_t(2) << 61) | (uint64_t(1) << 46) | (uint64_t(64) << 32) | (uint64_t(1) << 16);
#define MAKE_DESC(addr) (SMEM_DESC_BASE_SW128 | ((uint64_t)((addr) >> 4) & 0x3FFF))

#if HAS_TCGEN05
__device__ __forceinline__ uint32_t elect1() {
    uint32_t p;
    asm volatile("{ .reg .pred p; elect.sync _|p, 0xFFFFFFFF; selp.b32 %0,1,0,p; }" : "=r"(p));
    return p;
}
__device__ __forceinline__ void mma_f16_ss(uint32_t d_tmem, uint64_t a_desc,
                                           uint64_t b_desc, uint32_t idesc, int en)
{
    asm volatile(
        "{\n\t.reg .pred p;\n\t"
        "setp.ne.u32 p, %4, 0;\n\t"
        "tcgen05.mma.cta_group::1.kind::f16 [%0], %1, %2, %3, {%5,%5,%5,%5}, p;\n\t}"
        :: "r"(d_tmem), "l"(a_desc), "l"(b_desc), "r"(idesc), "r"(en), "r"(0u)
        : "memory");
}
__device__ __forceinline__ void mma_f16_ts(uint32_t d_tmem, uint32_t a_tmem,
                                           uint64_t b_desc, uint32_t idesc, int en)
{
    asm volatile(
        "{\n\t.reg .pred p;\n\t"
        "setp.ne.u32 p, %4, 0;\n\t"
        "tcgen05.mma.cta_group::1.kind::f16 [%0], [%1], %2, %3, {%5,%5,%5,%5}, p;\n\t}"
        :: "r"(d_tmem), "r"(a_tmem), "l"(b_desc), "r"(idesc), "r"(en), "r"(0u)
        : "memory");
}
__device__ __forceinline__ void cp16(uint32_t dst, const void* src) {
    asm volatile("cp.async.cg.shared.global [%0], [%1], 16;" :: "r"(dst), "l"(src));
}
__device__ __forceinline__ void cp_commit() { asm volatile("cp.async.commit_group;" ::: "memory"); }
__device__ __forceinline__ void cp_wait0()  { asm volatile("cp.async.wait_group 0;" ::: "memory"); }
__device__ __forceinline__ void cp_wait1()  { asm volatile("cp.async.wait_group 1;" ::: "memory"); }
#define MBAR_WAIT(mbar, par) do {                                              \
    asm volatile(                                                              \
        "{\n\t.reg .pred P1;\n\t"                                              \
        "WL_%=:\n\t"                                                           \
        "mbarrier.try_wait.parity.acquire.cta.shared::cta.b64 P1, [%0], %1, 0x989680;\n\t" \
        "@P1 bra.uni WD_%=;\n\t"                                               \
        "bra.uni WL_%=;\n\t"                                                   \
        "WD_%=:\n\t}" :: "r"(mbar), "r"(par) : "memory");                      \
} while(0)
#define TCOMMIT(mbar)                                                          \
    asm volatile(                                                              \
        "tcgen05.commit.cta_group::1.mbarrier::arrive::one.shared::cluster.b64 [%0];" \
        :: "r"(mbar) : "memory")
#define LDTM32(r, addr)                                                        \
    asm volatile(                                                              \
        "tcgen05.ld.sync.aligned.32x32b.x32.b32 "                              \
        "{%0,%1,%2,%3,%4,%5,%6,%7,%8,%9,%10,%11,%12,%13,%14,%15,"              \
        "%16,%17,%18,%19,%20,%21,%22,%23,%24,%25,%26,%27,%28,%29,%30,%31}, [%32];" \
        : "=r"(r[0]),"=r"(r[1]),"=r"(r[2]),"=r"(r[3]),"=r"(r[4]),"=r"(r[5]),"=r"(r[6]),"=r"(r[7]), \
          "=r"(r[8]),"=r"(r[9]),"=r"(r[10]),"=r"(r[11]),"=r"(r[12]),"=r"(r[13]),"=r"(r[14]),"=r"(r[15]), \
          "=r"(r[16]),"=r"(r[17]),"=r"(r[18]),"=r"(r[19]),"=r"(r[20]),"=r"(r[21]),"=r"(r[22]),"=r"(r[23]), \
          "=r"(r[24]),"=r"(r[25]),"=r"(r[26]),"=r"(r[27]),"=r"(r[28]),"=r"(r[29]),"=r"(r[30]),"=r"(r[31]) \
        : "r"(addr))
#define STTM32(addr, r)                                                        \
    asm volatile(                                                              \
        "tcgen05.st.sync.aligned.32x32b.x32.b32 [%0], "                        \
        "{%1,%2,%3,%4,%5,%6,%7,%8,%9,%10,%11,%12,%13,%14,%15,%16,"             \
        "%17,%18,%19,%20,%21,%22,%23,%24,%25,%26,%27,%28,%29,%30,%31,%32};"    \
        :: "r"(addr),                                                          \
           "r"(r[0]),"r"(r[1]),"r"(r[2]),"r"(r[3]),"r"(r[4]),"r"(r[5]),"r"(r[6]),"r"(r[7]), \
           "r"(r[8]),"r"(r[9]),"r"(r[10]),"r"(r[11]),"r"(r[12]),"r"(r[13]),"r"(r[14]),"r"(r[15]), \
           "r"(r[16]),"r"(r[17]),"r"(r[18]),"r"(r[19]),"r"(r[20]),"r"(r[21]),"r"(r[22]),"r"(r[23]), \
           "r"(r[24]),"r"(r[25]),"r"(r[26]),"r"(r[27]),"r"(r[28]),"r"(r[29]),"r"(r[30]),"r"(r[31]) \
        : "memory")
#endif

__device__ __forceinline__ ushort bf_hi_us(float v, float& rem) {
    __nv_bfloat16 hb = __float2bfloat16(v);
    rem = v - __bfloat162float(hb);
    return *reinterpret_cast<ushort*>(&hb);
}
__device__ __forceinline__ ushort bf_us(float v) {
    __nv_bfloat16 b = __float2bfloat16(v);
    return *reinterpret_cast<ushort*>(&b);
}

// ---------------- merged prep ------------------------------------------------------
// blocks [0,6250): emb normalize + hi/lo split
// blocks [6250,6698): weight transpose + split
// blocks [6698,6748): posw1[l][n] = pos_emb[l] @ w1_top   (fp32 exact)
// blocks [6748,7004): hs/lens/hsw1 per batch b
#define NPE_BLOCKS 6250
#define W_BASE  NPE_BLOCKS
#define PW_BASE (NPE_BLOCKS + 448)
#define HS_BASE (PW_BASE + 50)
#define PREP_GRID (HS_BASE + 256)
__global__ void k_prep(const float* __restrict__ emb, const float* __restrict__ w1,
                       const float* __restrict__ glu1_w, const float* __restrict__ att_w2,
                       const float* __restrict__ pos_emb, const float* __restrict__ hidden,
                       const int* __restrict__ mask, const float* __restrict__ att_w1)
{
    __shared__ float sm_buf[DD];
    int t = threadIdx.x;
    if (blockIdx.x < NPE_BLOCKS) {
        int w = t >> 5, lane = t & 31;
        int v = blockIdx.x*8 + w;
        if (v >= VM1) return;
        float4 x = *(const float4*)(emb + (size_t)(1 + v)*DD + lane*4);
        float s = x.x*x.x + x.y*x.y + x.z*x.z + x.w*x.w;
        #pragma unroll
        for (int o = 16; o > 0; o >>= 1) s += __shfl_xor_sync(0xffffffffu, s, o);
        float inv = 1.0f / fmaxf(sqrtf(s), EPS_N);
        float n[4] = {x.x*inv, x.y*inv, x.z*inv, x.w*inv};
        __nv_bfloat16 hi[4], lo[4];
        #pragma unroll
        for (int i = 0; i < 4; i++) {
            hi[i] = __float2bfloat16(n[i]);
            lo[i] = __float2bfloat16(n[i] - __bfloat162float(hi[i]));
        }
        *(uint64_t*)(&g_emb_hi[(size_t)v*DD + lane*4]) = *(uint64_t*)hi;
        *(uint64_t*)(&g_emb_lo[(size_t)v*DD + lane*4]) = *(uint64_t*)lo;
    } else if (blockIdx.x < PW_BASE) {
        int i = (blockIdx.x - W_BASE)*256 + t;
        float v; __nv_bfloat16 hi, lo;
        if (i < 32768) {                 // w1 [256k,128n] -> [128n][256k]
            int n = i >> 8, k = i & 255;
            v = w1[k*128 + n];
            hi = __float2bfloat16(v); lo = __float2bfloat16(v - __bfloat162float(hi));
            g_w1b_hi[i] = hi; g_w1b_lo[i] = lo;
        } else if (i < 32768 + 65536) {  // glu1_w [128k,512n] -> [512n][128k]
            int j = i - 32768;
            int n = j >> 7, k = j & 127;
            v = glu1_w[k*512 + n];
            hi = __float2bfloat16(v); lo = __float2bfloat16(v - __bfloat162float(hi));
            g_glub_hi[j] = hi; g_glub_lo[j] = lo;
        } else if (i < 114688) {         // att_w2 [128k,128n] -> [128n][128k]
            int j = i - 98304;
            int n = j >> 7, k = j & 127;
            v = att_w2[k*128 + n];
            hi = __float2bfloat16(v); lo = __float2bfloat16(v - __bfloat162float(hi));
            g_aw2b_hi[j] = hi; g_aw2b_lo[j] = lo;
        }
    } else if (blockIdx.x < HS_BASE) {
        int l = blockIdx.x - PW_BASE;
        if (t < 128) sm_buf[t] = pos_emb[l*DD + t];
        __syncthreads();
        if (t < 128) {
            float a = 0.f;
            #pragma unroll 8
            for (int k = 0; k < 128; k++) a += sm_buf[k] * w1[k*128 + t];
            g_posw1[l*DD + t] = a;
        }
    } else {
        int b = blockIdx.x - HS_BASE;
        float hsv = 0.f;
        if (t < 128) {
            float acc = 0.f, sm = 0.f;
            for (int l = 0; l < LL; l++) {
                float mk = (float)mask[b*LL + l];
                sm  += mk;
                acc += hidden[(size_t)(b*LL + l)*DD + t] * mk;
            }
            hsv = acc / sm;
            sm_buf[t] = hsv;
            if (t == 0) g_lens[b] = sm - (float)LEN_OPT;
        }
        __syncthreads();
        if (t < 128) {
            float a2 = 0.f;
            #pragma unroll 8
            for (int e = 0; e < DD; e++) a2 += sm_buf[e] * att_w1[e*DD + t];
            g_hsw1[b*DD + t] = a2;
        }
    }
}

// ---------------- fused front kernel ------------------------------------------------
// One CTA per 128-token mtile. Computes nh, alpha, beta with NO intermediate DRAM.
//  nh  = tanh(hidden@w1_bot + posw1[l])     (D cols 0-127)
//  att = hidden@aw2b                        (D cols 128-255)
//  glu = nh@glub (nh kept in smem as A)     (D cols 0-511 reused)
#define FF_TMEM  0
#define FF_MBAR  8
#define FF_BIAS  64
#define FF_W2    2176
#define FF_ATTV  4288
#define FF_ALPHA 6400
#define FF_POSW1 8448                        // 50*129*4 = 25800 -> ends 34248
#define FF_AHID  34816                       // 64KB (hi/lo)
#define FF_ANH   100352                      // 64KB (hi/lo)
#define FF_B0    165888                      // 32KB (hi 16K / lo 16K)
#define FF_B1    198656                      // 32KB
#define FF_SMEM  231424
#define IDESC64 ((1u<<4)|(1u<<7)|(1u<<10)|(8u<<17)|(8u<<24))

#if HAS_TCGEN05
// load one B chunk: 64 rows x 128 k bf16 hi+lo (32KB) via cp.async
__device__ __forceinline__ void f_load_chunk(uint32_t dst, const __nv_bfloat16* hi,
                                             const __nv_bfloat16* lo, int row0,
                                             int KD, int col0, int tid)
{
    #pragma unroll 8
    for (int i = tid; i < 2048; i += 256) {
        int half = i >> 10, rem = i & 1023;
        int r = rem >> 4, c8 = rem & 15;
        const __nv_bfloat16* src = (half ? lo : hi)
            + (size_t)(row0 + r)*KD + col0 + (c8 >> 3)*64 + (c8 & 7)*8;
        uint32_t byte = (uint32_t)((c8 >> 3)*8 + (r >> 3))*1024u
                      + (uint32_t)(r & 7)*128u + (uint32_t)(c8 & 7)*16u;
        cp16(dst + half*16384u + SWZ128(byte), src);
    }
    cp_commit();
}
// MMA one 128x64x128 chunk (3-pass hi/lo split), D at column base d
__device__ __forceinline__ void f_mma_chunk(uint32_t d, uint32_t sbase,
                                            uint32_t aoff, uint32_t boff)
{
    uint64_t dAh = MAKE_DESC(sbase + aoff), dAl = MAKE_DESC(sbase + aoff + 32768);
    uint64_t dBh = MAKE_DESC(sbase + boff), dBl = MAKE_DESC(sbase + boff + 16384);
    uint64_t ad[3] = { dAh, dAh, dAl };
    uint64_t bd[3] = { dBh, dBl, dBh };
    #pragma unroll
    for (int p = 0; p < 3; p++)
        #pragma unroll
        for (int s = 0; s < 8; s++)
            mma_f16_ss(d, ad[p] + (uint64_t)((s >> 2)*1024 + (s & 3)*2),
                       bd[p] + (uint64_t)((s >> 2)*512 + (s & 3)*2),
                       IDESC64, !(p == 0 && s == 0));
}
#endif

__global__ void __launch_bounds__(256, 1) k_front(
    const float* __restrict__ hidden, const float* __restrict__ glu1_b,
    const float* __restrict__ w2, const float* __restrict__ att_v,
    const int* __restrict__ mask, const float* __restrict__ pos_emb,
    const float* __restrict__ w1)
{
#if HAS_TCGEN05
    extern __shared__ char smem[];
    uint32_t sbase = smem_u32(smem);
    int tid = threadIdx.x, wid = tid >> 5, lane = tid & 31;
    int mtile = blockIdx.x;
    uint32_t mbar = sbase + FF_MBAR;

    if (tid == 0)
        asm volatile("mbarrier.init.shared.b64 [%0], 1;" :: "r"(mbar) : "memory");
    if (wid == 0)
        asm volatile("tcgen05.alloc.cta_group::1.sync.aligned.shared::cta.b32 [%0], %1;"
                     :: "r"(sbase + FF_TMEM), "r"(512u) : "memory");
    __syncthreads();
    uint32_t tmem;
    asm volatile("ld.shared.b32 %0, [%1];" : "=r"(tmem) : "r"(sbase + FF_TMEM));

    // prefetch nh B chunks (w1_bot halves)
    f_load_chunk(sbase + FF_B0, g_w1b_hi, g_w1b_lo,  0, 256, 128, tid);
    f_load_chunk(sbase + FF_B1, g_w1b_hi, g_w1b_lo, 64, 256, 128, tid);

    // stage A = hidden tile (fp32 -> hi/lo split, swizzled)
    for (int i = tid; i < 128*16; i += 256) {
        int r = i >> 4, c8 = i & 15;
        int m = mtile*128 + r;
        int col = (c8 >> 3)*64 + (c8 & 7)*8;
        const float* src = hidden + (size_t)m*DD + col;
        float f[8];
        *(float4*)f       = *(const float4*)src;
        *(float4*)(f + 4) = *(const float4*)(src + 4);
        __align__(16) ushort h[8], l[8];
        #pragma unroll
        for (int q = 0; q < 8; q++) { float rem; h[q] = bf_hi_us(f[q], rem); l[q] = bf_us(rem); }
        uint32_t byte = (uint32_t)((c8 >> 3)*16 + (r >> 3))*1024u
                      + (uint32_t)(r & 7)*128u + (uint32_t)(c8 & 7)*16u;
        uint32_t sw = SWZ128(byte);
        *(uint4*)(smem + FF_AHID + sw)         = *(uint4*)h;
        *(uint4*)(smem + FF_AHID + 32768 + sw) = *(uint4*)l;
    }
    // stage aux: bias, w2, att_v, posw1 (padded rows of 129)
    {
        float* bias = (float*)(smem + FF_BIAS);
        float* w2s  = (float*)(smem + FF_W2);
        float* avs  = (float*)(smem + FF_ATTV);
        for (int i = tid; i < 512; i += 256) { bias[i] = glu1_b[i]; w2s[i] = w2[i]; avs[i] = att_v[i]; }
        float* pw = (float*)(smem + FF_POSW1);
        for (int i = tid; i < 50*128; i += 256) pw[(i >> 7)*129 + (i & 127)] = g_posw1[i];
    }
    cp_wait0();
    __syncthreads();

    // nh MMAs (D cols 0-63, 64-127)
    if (wid == 0 && elect1()) {
        asm volatile("fence.proxy.async.shared::cta;" ::: "memory");
        f_mma_chunk(tmem +  0, sbase, FF_AHID, FF_B0);
        f_mma_chunk(tmem + 64, sbase, FF_AHID, FF_B1);
        TCOMMIT(mbar);
    }
    MBAR_WAIT(mbar, 0u);

    // att B chunks
    f_load_chunk(sbase + FF_B0, g_aw2b_hi, g_aw2b_lo,  0, 128, 0, tid);
    f_load_chunk(sbase + FF_B1, g_aw2b_hi, g_aw2b_lo, 64, 128, 0, tid);
    cp_wait0();
    __syncthreads();
    if (wid == 0 && elect1()) {
        asm volatile("fence.proxy.async.shared::cta;" ::: "memory");
        f_mma_chunk(tmem + 128, sbase, FF_AHID, FF_B0);
        f_mma_chunk(tmem + 192, sbase, FF_AHID, FF_B1);
        TCOMMIT(mbar);
    }
    MBAR_WAIT(mbar, 1u);
    asm volatile("tcgen05.fence::after_thread_sync;" ::: "memory");

    // prefetch first GLU B chunks during epilogue
    f_load_chunk(sbase + FF_B0, g_glub_hi, g_glub_lo,  0, 128, 0, tid);
    f_load_chunk(sbase + FF_B1, g_glub_hi, g_glub_lo, 64, 128, 0, tid);

    // epilogue: warps 0-3: nh -> ANH smem; warps 4-7: alpha -> smem
    {
        int sub = wid & 3;
        int mloc = sub*32 + lane;
        int mglob = mtile*128 + mloc;
        if (wid < 4) {
            const float* prow = (const float*)(smem + FF_POSW1) + (mglob % LL)*129;
            #pragma unroll 1
            for (int ch = 0; ch < 4; ch++) {
                uint32_t r[32];
                LDTM32(r, tmem + ch*32);
                asm volatile("tcgen05.wait::ld.sync.aligned;" ::: "memory");
                #pragma unroll
                for (int q = 0; q < 4; q++) {
                    __align__(16) ushort h8[8], l8[8];
                    #pragma unroll
                    for (int u = 0; u < 8; u++) {
                        int c = ch*32 + q*8 + u;
                        float v = tanhf(__uint_as_float(r[q*8 + u]) + prow[c]);
                        float rem; h8[u] = bf_hi_us(v, rem); l8[u] = bf_us(rem);
                    }
                    int c8 = ch*4 + q;
                    uint32_t byte = (uint32_t)((c8 >> 3)*16 + (mloc >> 3))*1024u
                                  + (uint32_t)(mloc & 7)*128u + (uint32_t)(c8 & 7)*16u;
                    uint32_t sw = SWZ128(byte);
                    *(uint4*)(smem + FF_ANH + sw)         = *(uint4*)h8;
                    *(uint4*)(smem + FF_ANH + 32768 + sw) = *(uint4*)l8;
                }
            }
        } else {
            const float* hsrow = g_hsw1 + (mglob / LL)*DD;
            const float* avs = (const float*)(smem + FF_ATTV);
            float acc[4] = {};
            #pragma unroll 1
            for (int ch = 0; ch < 4; ch++) {
                uint32_t r[32];
                LDTM32(r, tmem + 128 + ch*32);
                asm volatile("tcgen05.wait::ld.sync.aligned;" ::: "memory");
                #pragma unroll
                for (int j = 0; j < 32; j++) {
                    int c = ch*32 + j;
                    float t = tanhf(__uint_as_float(r[j]) + hsrow[c]);
                    #pragma unroll
                    for (int k = 0; k < 4; k++) acc[k] += t * avs[c*4 + k];
                }
            }
            float* al = (float*)(smem + FF_ALPHA);
            #pragma unroll
            for (int k = 0; k < 4; k++) al[mloc*4 + k] = sigmoidf(acc[k]);
        }
        asm volatile("tcgen05.fence::before_thread_sync;" ::: "memory");
    }
    cp_wait0();
    __syncthreads();

    // GLU MMAs: 8 chunks of 64 n, D cols c*64 (reusing 0-511)
    int ph = 0;
    for (int p = 0; p < 4; p++) {
        if (wid == 0 && elect1()) {
            asm volatile("tcgen05.fence::after_thread_sync;" ::: "memory");
            asm volatile("fence.proxy.async.shared::cta;" ::: "memory");
            f_mma_chunk(tmem + (2*p    )*64, sbase, FF_ANH, FF_B0);
            f_mma_chunk(tmem + (2*p + 1)*64, sbase, FF_ANH, FF_B1);
            TCOMMIT(mbar);
        }
        MBAR_WAIT(mbar, (uint32_t)(ph & 1));
        ph++;
        if (p < 3) {
            f_load_chunk(sbase + FF_B0, g_glub_hi, g_glub_lo, (2*p + 2)*64, 128, 0, tid);
            f_load_chunk(sbase + FF_B1, g_glub_hi, g_glub_lo, (2*p + 3)*64, 128, 0, tid);
            cp_wait0();
            __syncthreads();
        }
    }
    asm volatile("tcgen05.fence::after_thread_sync;" ::: "memory");

    // GLU epilogue: 8 warps; warp w: sub=w&3, g=w>>2 -> interests k=2g, 2g+1
    {
        int sub = wid & 3, g = wid >> 2;
        int mloc = sub*32 + lane;
        int mglob = mtile*128 + mloc;
        const float* bias = (const float*)(smem + FF_BIAS);
        const float* w2s  = (const float*)(smem + FF_W2);
        float acc0 = 0.f, acc1 = 0.f;
        #pragma unroll 1
        for (int cc = 0; cc < 8; cc++) {
            int ch = g*8 + cc;
            uint32_t r[32];
            LDTM32(r, tmem + ch*32);
            asm volatile("tcgen05.wait::ld.sync.aligned;" ::: "memory");
            int k = ch >> 2;
            float a = 0.f;
            #pragma unroll
            for (int j = 0; j < 32; j++) {
                int n = ch*32 + j;
                float s = sigmoidf(__uint_as_float(r[j]) + bias[n]);
                a += s * w2s[(n & 127)*4 + k];
            }
            if (cc < 4) acc0 += a; else acc1 += a;
        }
        const float* al = (const float*)(smem + FF_ALPHA);
        float mk = (float)mask[mglob];
        float2 o;
        o.x = acc0 * (0.5f + al[mloc*4 + 2*g    ]) * mk;
        o.y = acc1 * (0.5f + al[mloc*4 + 2*g + 1]) * mk;
        *(float2*)(g_beta + mglob*4 + 2*g) = o;
    }
    __syncthreads();
    if (wid == 0)
        asm volatile("tcgen05.dealloc.cta_group::1.sync.aligned.b32 %0, %1;"
                     :: "r"(tmem), "r"(512u));
#else
    // ---------- correct (slow) fallback for non-'a' compile targets ----------
    int tid = threadIdx.x;
    if (tid >= 128) return;
    int m = blockIdx.x*128 + tid;
    float nh[128];
    for (int n = 0; n < 128; n++) {
        float acc = 0.f;
        for (int k = 0; k < 128; k++) acc += pos_emb[(m % LL)*DD + k] * w1[k*128 + n];
        for (int k = 0; k < 128; k++) {
            float b = __bfloat162float(g_w1b_hi[n*256 + 128 + k]) + __bfloat162float(g_w1b_lo[n*256 + 128 + k]);
            acc += hidden[(size_t)m*DD + k] * b;
        }
        nh[n] = tanhf(acc);
    }
    float alpha[4] = {};
    for (int n = 0; n < 128; n++) {
        float x = 0.f;
        for (int k = 0; k < 128; k++)
            x += hidden[(size_t)m*DD + k] *
                 (__bfloat162float(g_aw2b_hi[n*128 + k]) + __bfloat162float(g_aw2b_lo[n*128 + k]));
        float t = tanhf(x + g_hsw1[(m / LL)*DD + n]);
        for (int k = 0; k < 4; k++) alpha[k] += t * att_v[n*4 + k];
    }
    for (int k = 0; k < 4; k++) alpha[k] = sigmoidf(alpha[k]);
    float acc[4] = {};
    for (int n = 0; n < 512; n++) {
        float x = 0.f;
        for (int k = 0; k < 128; k++)
            x += nh[k] * (__bfloat162float(g_glub_hi[n*128 + k]) + __bfloat162float(g_glub_lo[n*128 + k]));
        float s = sigmoidf(x + glu1_b[n]);
        acc[n >> 7] += s * w2[(n & 127)*4 + (n >> 7)];
    }
    float mk = (float)mask[m];
    for (int k = 0; k < 4; k++)
        g_beta[m*4 + k] = acc[k] * (0.5f + alpha[k]) * mk;
#endif
}

// ---------------- select (blocks 0..255) + loss (block 256) ------------------------
__global__ void k_sel_loss(const float* __restrict__ hidden, float* __restrict__ out_scalar)
{
    if (blockIdx.x < BB) {
        if (threadIdx.x >= 128) return;
        int b = blockIdx.x, t = threadIdx.x;
        float acc[4] = {};
        for (int l = 0; l < LL; l++) {
            float h = hidden[(size_t)(b*LL + l)*DD + t];
            float4 be = *(const float4*)(&g_beta[(b*LL + l)*4]);
            acc[0] += be.x*h; acc[1] += be.y*h; acc[2] += be.z*h; acc[3] += be.w*h;
        }
        #pragma unroll
        for (int k = 0; k < 4; k++) {
            float v = acc[k];
            __nv_bfloat16 hi = __float2bfloat16(v);
            __nv_bfloat16 lo = __float2bfloat16(v - __bfloat162float(hi));
            g_sel_hi[(b*4 + k)*DD + t] = hi;
            g_sel_lo[(b*4 + k)*DD + t] = lo;
        }
    } else {
        int b = threadIdx.x;
        float n2[4] = {};
        for (int l = 0; l < LL; l++) {
            float4 be = *(const float4*)(&g_beta[(b*LL + l)*4]);
            n2[0]+=be.x*be.x; n2[1]+=be.y*be.y; n2[2]+=be.z*be.z; n2[3]+=be.w*be.w;
        }
        float inv[4];
        #pragma unroll
        for (int k = 0; k < 4; k++) inv[k] = 1.0f / fmaxf(sqrtf(n2[k]), EPS_N);
        float G[6] = {};
        for (int l = 0; l < LL; l++) {
            float4 be = *(const float4*)(&g_beta[(b*LL + l)*4]);
            float v0=be.x*inv[0], v1=be.y*inv[1], v2=be.z*inv[2], v3=be.w*inv[3];
            G[0]+=v0*v1; G[1]+=v0*v2; G[2]+=v0*v3;
            G[3]+=v1*v2; G[4]+=v1*v3; G[5]+=v2*v3;
        }
        float sim = 0.f;
        #pragma unroll
        for (int i = 0; i < 6; i++) sim += fabsf(G[i]);
        sim *= (2.0f / (KK*(KK-1)));
        float lossb = sigmoidf(sim * g_lens[b]);
        __shared__ float red[BB];
        red[b] = lossb;  __syncthreads();
        for (int s = BB/2; s > 0; s >>= 1) {
            if (b < s) red[b] += red[b + s];
            __syncthreads();
        }
        if (b == 0) *out_scalar = red[0] * BETA_S;
    }
}

// ---------------- scores: persistent CTAs, TS-mode MMA, 8-warp epilogue ------------
#define SC_TILES 391
#define SC_STRIDE 18
#define S_IDESC ((1u<<4) | (1u<<7) | (1u<<10) | ((128/8)<<17) | (8u<<24))
#define S2_TMEM  0
#define S2_MBAR0 8
#define S2_MBAR1 16
#define S2_B0    1024
#define S2_B1    (1024 + 65536)
#define S2_STG   (1024 + 131072)
#define S2_SMEM_TOT (132096 + 8*32*33*4)

#if HAS_TCGEN05
__device__ __forceinline__ void s2_load_b(uint32_t bufbase, int vtile, int tid)
{
    int vbase = vtile * 128;
    #pragma unroll 4
    for (int i = tid; i < 4096; i += 256) {
        int half = i >> 11, rem = i & 2047;
        int r = rem >> 4, c8 = rem & 15;
        int v = vbase + r; if (v > VM1 - 1) v = VM1 - 1;
        const __nv_bfloat16* src = (half ? g_emb_lo : g_emb_hi)
                                 + (size_t)v*DD + (c8 >> 3)*64 + (c8 & 7)*8;
        uint32_t byte = (uint32_t)((c8 >> 3)*16 + (r >> 3))*1024u
                      + (uint32_t)(r & 7)*128u + (uint32_t)(c8 & 7)*16u;
        cp16(bufbase + half*32768u + SWZ128(byte), src);
    }
    cp_commit();
}
__device__ __forceinline__ void s2_mma(uint32_t tmem, int dhalf, uint32_t sbase,
                                       uint32_t bufoff, uint32_t mbar)
{
    asm volatile("fence.proxy.async.shared::cta;" ::: "memory");
    uint64_t dBh = MAKE_DESC(sbase + bufoff);
    uint64_t dBl = MAKE_DESC(sbase + bufoff + 32768);
    uint32_t d  = tmem + (dhalf << 7);
    uint32_t aH = tmem + 256, aL = tmem + 320;
    uint32_t ap[3] = { aH, aH, aL };
    uint64_t bp[3] = { dBh, dBl, dBh };
    #pragma unroll
    for (int p = 0; p < 3; p++) {
        #pragma unroll
        for (int s = 0; s < 8; s++) {
            mma_f16_ts(d, ap[p] + s*8,
                       bp[p] + (uint64_t)((s >> 2)*1024 + (s & 3)*2),
                       S_IDESC, !(p == 0 && s == 0));
        }
    }
    asm volatile(
        "tcgen05.commit.cta_group::1.mbarrier::arrive::one.shared::cluster.b64 [%0];"
        :: "r"(mbar) : "memory");
}
#endif

__global__ void __launch_bounds__(256, 1) k_scores_mma(
        float* __restrict__ maxsc, float* __restrict__ scores)
{
#if HAS_TCGEN05
    extern __shared__ char smem[];
    uint32_t sbase = smem_u32(smem);
    int tid = threadIdx.x, wid = tid >> 5, lane = tid & 31;
    int mtile = blockIdx.x;
    int y = blockIdx.y;
    int nt = (SC_TILES - y + SC_STRIDE - 1) / SC_STRIDE;

    if (tid == 0) {
        asm volatile("mbarrier.init.shared.b64 [%0], 1;" :: "r"(sbase + S2_MBAR0) : "memory");
        asm volatile("mbarrier.init.shared.b64 [%0], 1;" :: "r"(sbase + S2_MBAR1) : "memory");
    }
    if (wid == 0)
        asm volatile("tcgen05.alloc.cta_group::1.sync.aligned.shared::cta.b32 [%0], %1;"
                     :: "r"(sbase + S2_TMEM), "r"(512u) : "memory");
    __syncthreads();
    uint32_t tmem;
    asm volatile("ld.shared.b32 %0, [%1];" : "=r"(tmem) : "r"(sbase + S2_TMEM));

    s2_load_b(sbase + S2_B0, y, tid);
    s2_load_b(sbase + S2_B1, y + SC_STRIDE, tid);
    if (tid < 128) {
        int m = mtile*128 + tid;
        const uint32_t* ph = (const uint32_t*)g_sel_hi + (size_t)m*64;
        const uint32_t* pl = (const uint32_t*)g_sel_lo + (size_t)m*64;
        uint32_t woff = (uint32_t)(tid >> 5) << 21;
        uint32_t a[32];
        #pragma unroll
        for (int q = 0; q < 32; q++) a[q] = ph[q];
        STTM32(tmem + 256 + woff, a);
        #pragma unroll
        for (int q = 0; q < 32; q++) a[q] = ph[32 + q];
        STTM32(tmem + 288 + woff, a);
        #pragma unroll
        for (int q = 0; q < 32; q++) a[q] = pl[q];
        STTM32(tmem + 320 + woff, a);
        #pragma unroll
        for (int q = 0; q < 32; q++) a[q] = pl[32 + q];
        STTM32(tmem + 352 + woff, a);
        asm volatile("tcgen05.wait::st.sync.aligned;" ::: "memory");
    }
    cp_wait1();
    __syncthreads();
    if (wid == 0 && elect1())
        s2_mma(tmem, 0, sbase, S2_B0, sbase + S2_MBAR0);

    int sub = wid & 3, h = wid >> 2;
    float* stg = (float*)(smem + S2_STG + wid*(32*33*4));

    for (int i = 0; i < nt; i++) {
        cp_wait0();
        MBAR_WAIT(sbase + ((i & 1) ? S2_MBAR1 : S2_MBAR0), (uint32_t)((i >> 1) & 1));
        asm volatile("tcgen05.fence::after_thread_sync;" ::: "memory");
        __syncthreads();

        if (i + 1 < nt && wid == 0 && elect1())
            s2_mma(tmem, (i + 1) & 1, sbase,
                   ((i + 1) & 1) ? S2_B1 : S2_B0,
                   sbase + (((i + 1) & 1) ? S2_MBAR1 : S2_MBAR0));
        if (i + 2 < nt)
            s2_load_b(sbase + ((i & 1) ? S2_B1 : S2_B0), y + (i + 2)*SC_STRIDE, tid);

        uint32_t dbase = tmem + ((i & 1) << 7);
        int vb = (y + i*SC_STRIDE)*128;
        #pragma unroll 1
        for (int cc = 0; cc < 2; cc++) {
            int col0 = h*64 + cc*32;
            uint32_t r[32];
            LDTM32(r, dbase + col0);
            asm volatile("tcgen05.wait::ld.sync.aligned;" ::: "memory");
            #pragma unroll
            for (int c = 0; c < 32; c++) stg[lane*33 + c] = __uint_as_float(r[c]);
            __syncwarp();
            int v = vb + col0 + lane;
            bool ok = v < VM1;
            #pragma unroll
            for (int lb = 0; lb < 8; lb++) {
                int b = mtile*32 + sub*8 + lb;
                float mx = -3.402823466e38f;
                #pragma unroll
                for (int j = 0; j < 4; j++) {
                    float x = stg[(lb*4 + j)*33 + lane];
                    if (ok) __stcs(&scores[((size_t)j*BB + b)*VM1 + v], x);
                    mx = fmaxf(mx, x);
                }
                if (ok) __stcs(&maxsc[(size_t)b*VM1 + v], mx);
            }
            __syncwarp();
        }
    }
    __syncthreads();
    if (wid == 0)
        asm volatile("tcgen05.dealloc.cta_group::1.sync.aligned.b32 %0, %1;"
                     :: "r"(tmem), "r"(512u));
#else
    int tid = threadIdx.x;
    int mtile = blockIdx.x;
    int y = blockIdx.y;
    for (int vt = y; vt < SC_TILES; vt += SC_STRIDE) {
        int vbase = vt*128;
        for (int p = tid; p < 32*128; p += 256) {
            int bl = p >> 7, vv = vbase + (p & 127);
            if (vv >= VM1) continue;
            int b = mtile*32 + bl;
            float mx = -3.402823466e38f;
            for (int k = 0; k < 4; k++) {
                int m = (b*4 + k);
                float acc = 0.f;
                for (int d = 0; d < DD; d++) {
                    float a = __bfloat162float(g_sel_hi[m*DD + d]) + __bfloat162float(g_sel_lo[m*DD + d]);
                    float e = __bfloat162float(g_emb_hi[(size_t)vv*DD + d]) + __bfloat162float(g_emb_lo[(size_t)vv*DD + d]);
                    acc += a * e;
                }
                scores[((size_t)k*BB + b)*VM1 + vv] = acc;
                mx = fmaxf(mx, acc);
            }
            maxsc[(size_t)b*VM1 + vv] = mx;
        }
    }
#endif
}

// ---------------- launch ------------------------------------------------------------
extern "C" void kernel_launch(void* const* d_in, const int* in_sizes, int n_in,
                              void* d_out, int out_size)
{
    const float* hidden  = (const float*)d_in[0];
    const int*   mask    = (const int*)  d_in[1];
    const float* pos_emb = (const float*)d_in[2];
    const float* w1      = (const float*)d_in[3];
    const float* w2      = (const float*)d_in[4];
    const float* glu1_w  = (const float*)d_in[5];
    const float* glu1_b  = (const float*)d_in[6];
    const float* att_w1  = (const float*)d_in[7];
    const float* att_w2  = (const float*)d_in[8];
    const float* att_v   = (const float*)d_in[9];
    const float* emb     = (const float*)d_in[10];

    float* out    = (float*)d_out;
    float* maxsc  = out;                                   // [B, Vm1]
    float* scalar = out + (size_t)BB*VM1;                  // [1]
    float* scores = out + (size_t)BB*VM1 + 1;              // [K, B, Vm1]

    cudaFuncSetAttribute(k_scores_mma,
                         cudaFuncAttributeMaxDynamicSharedMemorySize, S2_SMEM_TOT);
    cudaFuncSetAttribute(k_front,
                         cudaFuncAttributeMaxDynamicSharedMemorySize, FF_SMEM);

    k_prep<<<PREP_GRID, 256>>>(emb, w1, glu1_w, att_w2, pos_emb, hidden, mask, att_w1);
    k_front<<<100, 256, FF_SMEM>>>(hidden, glu1_b, w2, att_v, mask, pos_emb, w1);
    k_sel_loss<<<BB + 1, 256>>>(hidden, scalar);
    k_scores_mma<<<dim3(8, SC_STRIDE), 256, S2_SMEM_TOT>>>(maxsc, scores);
}